// round 14
// baseline (speedup 1.0000x reference)
#include <cuda_runtime.h>
#include <cuda_fp16.h>
#include <mma.h>
#include <cstdint>

using namespace nvcuda;

// ---------------------------------------------------------------------------
// MoCoGraph: two 2-layer GAT encoders + MoCo logits.
// GEMMs: fp16 single-pass wmma (fp32 accum), CTA 192x128, 8 warps,
//        warp tile 48x64, BK=64 cp.async double-buffer, 2 CTAs/SM, fp32 out.
// H converted to fp16 (bulk kernel) for the attention read path.
// Attention: CSR gather over fp16 H, fused softmax+aggregate epilogue.
// Logits: smem-tiled fp32 GEMM.
// ---------------------------------------------------------------------------

#define NMAX   10240
#define MPAD   10368     // multiple of 192 >= N
#define ETMAX  180224
#define F512   512
#define C128   128
#define CAP    512
#define KPAD1  1024

typedef __half hf;

// ------------------------- device scratch (no mallocs) ---------------------
__device__ float g_H  [2 * (size_t)MPAD * F512];
__device__ hf    g_A1 [2 * (size_t)MPAD * KPAD1];   // also reused as fp16 H copy
__device__ hf    g_A2 [2 * (size_t)MPAD * F512];    // pad rows stay 0 (zero-init)
__device__ hf    g_W1 [2 * KPAD1 * F512];
__device__ hf    g_W2 [2 * F512 * F512];
__device__ float g_asrc[2 * NMAX * 4];
__device__ float g_adst[2 * NMAX * 4];
__device__ float g_seedq[(size_t)NMAX * C128];
__device__ float g_seedk[(size_t)NMAX * C128];
__device__ float g_ask1m[F512], g_adk1m[F512], g_bk1m[F512];
__device__ float g_ask2m[F512], g_adk2m[F512], g_bk2m[C128];
__device__ int g_deg[NMAX];
__device__ int g_off[NMAX + 1];
__device__ int g_cur[NMAX];
__device__ int g_csrc[ETMAX];
__device__ float g_aggr2[2 * (size_t)NMAX * F512 / 4];   // layer-2 fp32 out (B rows)

// ------------------------------ helpers ------------------------------------
__device__ __forceinline__ uint32_t smem_u32(const void* p) {
    uint32_t a;
    asm("{ .reg .u64 t; cvta.to.shared.u64 t, %1; cvt.u32.u64 %0, t; }" : "=r"(a) : "l"(p));
    return a;
}
__device__ __forceinline__ void cp_async16(uint32_t s, const void* g) {
    asm volatile("cp.async.cg.shared.global [%0], [%1], 16;" :: "r"(s), "l"(g));
}
#define CP_COMMIT() asm volatile("cp.async.commit_group;" ::: "memory")
#define CP_WAIT(n)  asm volatile("cp.async.wait_group %0;" :: "n"(n) : "memory")

// ------------------------------ prep kernels -------------------------------
__global__ void conv_pad2_kernel(const float* __restrict__ in0,
                                 const float* __restrict__ in1,
                                 int M, int K, int Kp, long total,
                                 hf* __restrict__ out) {
    long idx = (long)blockIdx.x * blockDim.x + threadIdx.x;
    if (idx >= total) return;
    const float* in = blockIdx.y ? in1 : in0;
    size_t o = (size_t)blockIdx.y * total + idx;
    int r = (int)(idx / Kp), c = (int)(idx % Kp);
    float v = (r < M && c < K) ? in[(size_t)r * K + c] : 0.f;
    out[o] = __float2half_rn(v);
}

// bulk fp32 -> fp16 convert (vectorized: 4 floats -> 4 halves per thread)
__global__ void f2h_kernel(const float* __restrict__ in, hf* __restrict__ out,
                           long n4) {
    long i = (long)blockIdx.x * blockDim.x + threadIdx.x;
    if (i >= n4) return;
    float4 v = *(const float4*)(in + i * 4);
    __half2 lo = __floats2half2_rn(v.x, v.y);
    __half2 hi = __floats2half2_rn(v.z, v.w);
    *(uint2*)(out + i * 4) = make_uint2(*(uint32_t*)&lo, *(uint32_t*)&hi);
}

__global__ void wconv_all_kernel(const float* __restrict__ Wq1,
                                 const float* __restrict__ Wk1,
                                 const float* __restrict__ Wq2,
                                 const float* __restrict__ Wk2,
                                 int G, int Kp1,
                                 hf* __restrict__ W1, hf* __restrict__ W2) {
    long idx = (long)blockIdx.x * blockDim.x + threadIdx.x;
    const long s1 = (long)Kp1 * F512;
    const long s2 = (long)F512 * F512;
    if (idx < 2 * s1) {
        int z = idx >= s1;
        long j = idx - (long)z * s1;
        int r = (int)(j / F512);
        float v = 0.f;
        if (r < G) v = z ? (0.99f * Wk1[j] + 0.01f * Wq1[j]) : Wq1[j];
        W1[idx] = __float2half_rn(v);
    } else if (idx < 2 * s1 + 2 * s2) {
        long j2 = idx - 2 * s1;
        int z = j2 >= s2;
        long j = j2 - (long)z * s2;
        float v = z ? (0.99f * Wk2[j] + 0.01f * Wq2[j]) : Wq2[j];
        W2[j2] = __float2half_rn(v);
    }
}

__global__ void misc_prep_kernel(int N,
                                 int* __restrict__ deg, int* __restrict__ cur,
                                 const float* ask1, const float* asq1,
                                 const float* adk1, const float* adq1,
                                 const float* bk1,  const float* bq1,
                                 const float* ask2, const float* asq2,
                                 const float* adk2, const float* adq2,
                                 const float* bk2,  const float* bq2,
                                 float* o1, float* o2, float* o3,
                                 float* o4, float* o5, float* o6) {
    int idx = blockIdx.x * blockDim.x + threadIdx.x;
    if (idx < N) { deg[idx] = 0; return; }
    if (idx < 2 * N) { cur[idx - N] = 0; return; }
    int j = idx - 2 * N;
    if (j < 512)       o1[j]        = 0.99f * ask1[j]        + 0.01f * asq1[j];
    else if (j < 1024) o2[j - 512]  = 0.99f * adk1[j - 512]  + 0.01f * adq1[j - 512];
    else if (j < 1536) o3[j - 1024] = 0.99f * bk1[j - 1024]  + 0.01f * bq1[j - 1024];
    else if (j < 2048) o4[j - 1536] = 0.99f * ask2[j - 1536] + 0.01f * asq2[j - 1536];
    else if (j < 2560) o5[j - 2048] = 0.99f * adk2[j - 2048] + 0.01f * adq2[j - 2048];
    else if (j < 2688) o6[j - 2560] = 0.99f * bk2[j - 2560]  + 0.01f * bq2[j - 2560];
}

// ------------------------------- CSR build ---------------------------------
__global__ void csr_count_kernel(const int* __restrict__ ei, int E, int N,
                                 int* __restrict__ deg) {
    int i = blockIdx.x * blockDim.x + threadIdx.x;
    int ET = E + N;
    if (i >= ET) return;
    int d = (i < E) ? ei[E + i] : (i - E);
    atomicAdd(&deg[d], 1);
}

__global__ void csr_scan_kernel(const int* __restrict__ deg,
                                int* __restrict__ off, int N) {
    __shared__ int sh[1024];
    __shared__ int carry;
    int t = threadIdx.x;
    if (t == 0) carry = 0;
    __syncthreads();
    for (int base = 0; base < N; base += 1024) {
        int v = (base + t < N) ? deg[base + t] : 0;
        sh[t] = v;
        __syncthreads();
        for (int o = 1; o < 1024; o <<= 1) {
            int x = (t >= o) ? sh[t - o] : 0;
            __syncthreads();
            sh[t] += x;
            __syncthreads();
        }
        int excl = sh[t] - v + carry;
        if (base + t < N) off[base + t] = excl;
        __syncthreads();
        if (t == 1023) carry += sh[1023];
        __syncthreads();
    }
    if (t == 0) off[N] = carry;
}

__global__ void csr_fill_kernel(const int* __restrict__ ei, int E, int N,
                                const int* __restrict__ off,
                                int* __restrict__ cur,
                                int* __restrict__ csrc) {
    int i = blockIdx.x * blockDim.x + threadIdx.x;
    int ET = E + N;
    if (i >= ET) return;
    int s, d;
    if (i < E) { s = ei[i]; d = ei[E + i]; } else { s = d = i - E; }
    int pos = atomicAdd(&cur[d], 1);
    csrc[off[d] + pos] = s;
}

// ------ batched fp16 wmma GEMM: CTA 192x128, 8 warps, warp 48x64, BK=64 ----
#define BM 192
#define BN 128
#define BK 64
#define TGEMM 256
#define A_LD 72
#define B_LD 136
#define A_TILE_B 27648u
#define B_TILE_B 17408u
#define ST_A 0u
#define ST_B A_TILE_B
#define STAGE_B (A_TILE_B + B_TILE_B)   // 45056
#define SMEM_GEMM_BYTES (2 * STAGE_B)   // 90112 -> 2 CTAs/SM

__global__ void __launch_bounds__(TGEMM, 2)
gemm_wmma_fp16_kernel(int K, int Nn,
                      const hf* __restrict__ Ag0, const hf* __restrict__ Bg0,
                      float* __restrict__ C0,
                      size_t strideA, size_t strideB, size_t strideC) {
    extern __shared__ char smem[];
    const uint32_t sb = smem_u32(smem);
    const int tid = threadIdx.x;
    const int bn = blockIdx.x, bm = blockIdx.y;
    const size_t z = blockIdx.z;
    const hf* Ag = Ag0 + z * strideA;
    const hf* Bg = Bg0 + z * strideB;
    float* C = C0 + z * strideC;

    const int warpId = tid >> 5;
    const int wm = warpId & 3;
    const int wn = warpId >> 2;
    const int nk = K >> 6;

    const size_t aBase = (size_t)(bm * BM);
    const int cCol = bn * BN;

    auto load_stage = [&](int kt, uint32_t stg) {
#pragma unroll
        for (int i = 0; i < 6; i++) {
            int idx = tid + (i << 8);
            int ar = idx >> 3, as = (idx & 7) << 3;
            cp_async16(sb + stg + ST_A + (uint32_t)(ar * A_LD + as) * 2,
                       Ag + (aBase + ar) * K + kt * BK + as);
        }
#pragma unroll
        for (int i = 0; i < 4; i++) {
            int idx = tid + (i << 8);
            int br = idx >> 4, bs = (idx & 15) << 3;
            cp_async16(sb + stg + ST_B + (uint32_t)(br * B_LD + bs) * 2,
                       Bg + (size_t)(kt * BK + br) * Nn + cCol + bs);
        }
        CP_COMMIT();
    };

    wmma::fragment<wmma::accumulator, 16, 16, 16, float> acc[3][4];
#pragma unroll
    for (int i = 0; i < 3; i++)
#pragma unroll
        for (int j = 0; j < 4; j++) wmma::fill_fragment(acc[i][j], 0.0f);

    load_stage(0, 0);

    for (int kt = 0; kt < nk; kt++) {
        const uint32_t stg = (kt & 1) ? STAGE_B : 0u;
        if (kt + 1 < nk) {
            load_stage(kt + 1, (kt & 1) ? 0u : STAGE_B);
            CP_WAIT(1);
        } else {
            CP_WAIT(0);
        }
        __syncthreads();

        const hf* sA = (const hf*)(smem + stg + ST_A);
        const hf* sB = (const hf*)(smem + stg + ST_B);

#pragma unroll
        for (int kk = 0; kk < BK; kk += 16) {
            wmma::fragment<wmma::matrix_a, 16, 16, 16, hf, wmma::row_major> af[3];
#pragma unroll
            for (int i = 0; i < 3; i++)
                wmma::load_matrix_sync(af[i], sA + (wm * 48 + i * 16) * A_LD + kk, A_LD);
#pragma unroll
            for (int j = 0; j < 4; j++) {
                wmma::fragment<wmma::matrix_b, 16, 16, 16, hf, wmma::row_major> bf;
                wmma::load_matrix_sync(bf, sB + kk * B_LD + wn * 64 + j * 16, B_LD);
#pragma unroll
                for (int i = 0; i < 3; i++)
                    wmma::mma_sync(acc[i][j], af[i], bf, acc[i][j]);
            }
        }
        __syncthreads();
    }

#pragma unroll
    for (int i = 0; i < 3; i++) {
        int row = bm * BM + wm * 48 + i * 16;
#pragma unroll
        for (int j = 0; j < 4; j++) {
            int col = cCol + wn * 64 + j * 16;
            wmma::store_matrix_sync(&C[(size_t)row * Nn + col], acc[i][j],
                                    Nn, wmma::mem_row_major);
        }
    }
}

// ---------------------------- attention scores (fp16 H) --------------------
__global__ void att_scores_kernel(const hf* __restrict__ Hbase, size_t hstride,
                                  const float* __restrict__ s0, const float* __restrict__ d0,
                                  const float* __restrict__ s1, const float* __restrict__ d1,
                                  float* __restrict__ a_s_base,
                                  float* __restrict__ a_d_base, int N) {
    int n = blockIdx.x;
    if (n >= N) return;
    int z = blockIdx.y;
    const hf* Hf = Hbase + (size_t)z * hstride;
    const float* att_s = z ? s1 : s0;
    const float* att_d = z ? d1 : d0;
    float* a_s = a_s_base + (size_t)z * NMAX * 4;
    float* a_d = a_d_base + (size_t)z * NMAX * 4;

    int h = threadIdx.y;
    int lane = threadIdx.x;
    const hf* row = Hf + (size_t)n * F512 + h * C128;
    float ss = 0.f, sd = 0.f;
#pragma unroll
    for (int j = 0; j < 2; j++) {
        int c = (lane + 32 * j) * 2;
        float2 v = __half22float2(*(const __half2*)(row + c));
        ss += v.x * att_s[h * C128 + c] + v.y * att_s[h * C128 + c + 1];
        sd += v.x * att_d[h * C128 + c] + v.y * att_d[h * C128 + c + 1];
    }
#pragma unroll
    for (int o = 16; o > 0; o >>= 1) {
        ss += __shfl_down_sync(0xffffffffu, ss, o);
        sd += __shfl_down_sync(0xffffffffu, sd, o);
    }
    if (lane == 0) { a_s[n * 4 + h] = ss; a_d[n * 4 + h] = sd; }
}

// ---------------- fused per-dst softmax + aggregation (fp16 H) -------------
__device__ __forceinline__ float leaky(float e) { return e > 0.f ? e : 0.2f * e; }

__global__ __launch_bounds__(256)
void gat_attn_kernel(const hf* __restrict__ Hbase, size_t hstride,
                     const float4* __restrict__ a_s_base,
                     const float4* __restrict__ a_d_base,
                     const int* __restrict__ off,
                     const int* __restrict__ deg_arr,
                     const int* __restrict__ csrc,
                     const float* __restrict__ bias0,
                     const float* __restrict__ bias1,
                     hf* __restrict__ outh,
                     float* __restrict__ outf, size_t ostride,
                     size_t oslot) {
    int d = blockIdx.x;
    int z = blockIdx.y;
    int t = threadIdx.x;
    int lane = t & 31, wid = t >> 5;

    const hf* Hf = Hbase + (size_t)z * hstride;
    const float4* a_s4 = a_s_base + (size_t)z * NMAX;
    const float4* a_d4 = a_d_base + (size_t)z * NMAX;
    const float* bias = z ? bias1 : bias0;

    __shared__ int   s_list[CAP];
    __shared__ float w[CAP][4];
    __shared__ float red[8][4];
    __shared__ float mx_s[4], invd_s[4];

    const int start = off[d];
    const int deg = deg_arr[d];
    const float4 ad = a_d4[d];

    float m0 = -1e30f, m1 = -1e30f, m2 = -1e30f, m3 = -1e30f;
    for (int j = t; j < deg; j += 256) {
        int s = csrc[start + j];
        float4 as = a_s4[s];
        float e0 = leaky(as.x + ad.x);
        float e1 = leaky(as.y + ad.y);
        float e2 = leaky(as.z + ad.z);
        float e3 = leaky(as.w + ad.w);
        if (j < CAP) {
            s_list[j] = s;
            w[j][0] = e0; w[j][1] = e1; w[j][2] = e2; w[j][3] = e3;
        }
        m0 = fmaxf(m0, e0); m1 = fmaxf(m1, e1);
        m2 = fmaxf(m2, e2); m3 = fmaxf(m3, e3);
    }
#pragma unroll
    for (int o = 16; o > 0; o >>= 1) {
        m0 = fmaxf(m0, __shfl_xor_sync(0xffffffffu, m0, o));
        m1 = fmaxf(m1, __shfl_xor_sync(0xffffffffu, m1, o));
        m2 = fmaxf(m2, __shfl_xor_sync(0xffffffffu, m2, o));
        m3 = fmaxf(m3, __shfl_xor_sync(0xffffffffu, m3, o));
    }
    if (lane == 0) { red[wid][0] = m0; red[wid][1] = m1; red[wid][2] = m2; red[wid][3] = m3; }
    __syncthreads();
    if (t < 4) {
        float mm = -1e30f;
#pragma unroll
        for (int k = 0; k < 8; k++) mm = fmaxf(mm, red[k][t]);
        mx_s[t] = mm;
    }
    __syncthreads();
    const float mx0 = mx_s[0], mx1 = mx_s[1], mx2 = mx_s[2], mx3 = mx_s[3];

    float s0 = 0.f, s1 = 0.f, s2 = 0.f, s3 = 0.f;
    for (int j = t; j < deg; j += 256) {
        float e0, e1, e2, e3;
        if (j < CAP) {
            e0 = w[j][0]; e1 = w[j][1]; e2 = w[j][2]; e3 = w[j][3];
        } else {
            int s = csrc[start + j];
            float4 as = a_s4[s];
            e0 = leaky(as.x + ad.x); e1 = leaky(as.y + ad.y);
            e2 = leaky(as.z + ad.z); e3 = leaky(as.w + ad.w);
        }
        float x0 = expf(e0 - mx0), x1 = expf(e1 - mx1);
        float x2 = expf(e2 - mx2), x3 = expf(e3 - mx3);
        if (j < CAP) { w[j][0] = x0; w[j][1] = x1; w[j][2] = x2; w[j][3] = x3; }
        s0 += x0; s1 += x1; s2 += x2; s3 += x3;
    }
#pragma unroll
    for (int o = 16; o > 0; o >>= 1) {
        s0 += __shfl_xor_sync(0xffffffffu, s0, o);
        s1 += __shfl_xor_sync(0xffffffffu, s1, o);
        s2 += __shfl_xor_sync(0xffffffffu, s2, o);
        s3 += __shfl_xor_sync(0xffffffffu, s3, o);
    }
    __syncthreads();
    if (lane == 0) { red[wid][0] = s0; red[wid][1] = s1; red[wid][2] = s2; red[wid][3] = s3; }
    __syncthreads();
    if (t < 4) {
        float ssum = 0.f;
#pragma unroll
        for (int k = 0; k < 8; k++) ssum += red[k][t];
        invd_s[t] = 1.0f / (ssum + 1e-16f);
    }
    __syncthreads();

    const int c2 = t * 2;
    const int h = c2 >> 7;
    const float inv = invd_s[h];
    const float mxh = mx_s[h];
    float acc0 = 0.f, acc1 = 0.f;
    for (int j = 0; j < deg; j++) {
        int s;
        float ww;
        if (j < CAP) {
            s = s_list[j];
            ww = w[j][h];
        } else {
            s = csrc[start + j];
            const float* asp = (const float*)&a_s4[s];
            const float* adp = (const float*)&ad;
            ww = expf(leaky(asp[h] + adp[h]) - mxh);
        }
        float alpha = ww * inv;
        float2 v = __half22float2(*(const __half2*)(Hf + (size_t)s * F512 + c2));
        acc0 += v.x * alpha;
        acc1 += v.y * alpha;
    }
    if (outh) {
        acc0 = fmaxf(acc0 + bias[c2], 0.f);
        acc1 = fmaxf(acc1 + bias[c2 + 1], 0.f);
        size_t o = (size_t)z * oslot + (size_t)d * F512 + c2;
        *(__half2*)(outh + o) = __floats2half2_rn(acc0, acc1);
    } else {
        size_t o = (size_t)z * ostride + (size_t)d * F512 + c2;
        *(float2*)(outf + o) = make_float2(acc0, acc1);
    }
}

// layer-2 epilogue (batched)
__global__ void head_mean_norm_kernel(const float* __restrict__ aggr_base, size_t astride,
                                      const float* __restrict__ bias0,
                                      const float* __restrict__ bias1,
                                      float* __restrict__ outq,
                                      float* __restrict__ outk, int B) {
    int n = blockIdx.x;
    if (n >= B) return;
    int z = blockIdx.y;
    const float* aggr = aggr_base + (size_t)z * astride;
    const float* bias = z ? bias1 : bias0;
    float* outv = z ? outk : outq;
    int c = threadIdx.x;
    size_t base = (size_t)n * F512;
    float v = 0.25f * (aggr[base + c] + aggr[base + 128 + c] +
                       aggr[base + 256 + c] + aggr[base + 384 + c]) + bias[c];
    float s = v * v;
#pragma unroll
    for (int o = 16; o > 0; o >>= 1) s += __shfl_down_sync(0xffffffffu, s, o);
    __shared__ float red[4];
    if ((c & 31) == 0) red[c >> 5] = s;
    __syncthreads();
    float tot = red[0] + red[1] + red[2] + red[3];
    outv[(size_t)n * C128 + c] = v * rsqrtf(tot + 1e-24f);
}

// ---------------- logits: tiled fp32 GEMM out[B,1+R] ------------------------
#define LT 64
__global__ __launch_bounds__(256)
void logits_gemm_kernel(const float* __restrict__ q,
                        const float* __restrict__ kv,
                        const float* __restrict__ queue,
                        float* __restrict__ out, int B, int R,
                        long tail_off, long tail_len) {
    __shared__ float qt[LT][33];
    __shared__ float kt[32][LT + 4];
    const int tid = threadIdx.x;
    const int bx = blockIdx.x, by = blockIdx.y;
    const int tx = tid & 15, ty = tid >> 4;

    float acc[4][4];
#pragma unroll
    for (int i = 0; i < 4; i++)
#pragma unroll
        for (int j = 0; j < 4; j++) acc[i][j] = 0.f;

    for (int k0 = 0; k0 < 128; k0 += 32) {
#pragma unroll
        for (int i = 0; i < 8; i++) {
            int e = tid + i * 256;
            int r = e >> 5, c = e & 31;
            int gr = by * LT + r;
            qt[r][c] = (gr < B) ? q[(size_t)gr * 128 + k0 + c] : 0.f;
        }
#pragma unroll
        for (int i = 0; i < 8; i++) {
            int e = tid + i * 256;
            int r = e >> 6, c = e & 63;
            int gc = bx * LT + c;
            kt[r][c] = (gc < R) ? queue[(size_t)(k0 + r) * R + gc] : 0.f;
        }
        __syncthreads();
#pragma unroll
        for (int k = 0; k < 32; k++) {
            float ra[4], rb[4];
#pragma unroll
            for (int i = 0; i < 4; i++) ra[i] = qt[ty * 4 + i][k];
#pragma unroll
            for (int j = 0; j < 4; j++) rb[j] = kt[k][tx * 4 + j];
#pragma unroll
            for (int i = 0; i < 4; i++)
#pragma unroll
                for (int j = 0; j < 4; j++) acc[i][j] += ra[i] * rb[j];
        }
        __syncthreads();
    }

#pragma unroll
    for (int i = 0; i < 4; i++) {
        int row = by * LT + ty * 4 + i;
        if (row >= B) continue;
#pragma unroll
        for (int j = 0; j < 4; j++) {
            int col = bx * LT + tx * 4 + j;
            if (col < R)
                out[(size_t)row * (R + 1) + 1 + col] = acc[i][j] * 5.0f;
        }
    }

    if (bx == 0 && tid < LT) {
        int n = by * LT + tid;
        if (n < B) {
            const float* qr = q + (size_t)n * 128;
            const float* kr = kv + (size_t)n * 128;
            float s = 0.f;
#pragma unroll 4
            for (int c = 0; c < 128; c++) s += qr[c] * kr[c];
            out[(size_t)n * (R + 1)] = s * 5.0f;
        }
    }
    if (bx == 0 && by == 0) {
        for (long i = tid; i < tail_len; i += 256) out[tail_off + i] = 0.f;
    }
}

// ------------------------------- launch ------------------------------------
extern "C" void kernel_launch(void* const* d_in, const int* in_sizes, int n_in,
                              void* d_out, int out_size) {
    int base = n_in - 17;

    const float* im_q = (const float*)d_in[0];
    const float* im_k = (const float*)d_in[1];
    const int*   ei   = (const int*)d_in[2];

    const float* Wq1  = (const float*)d_in[base + 0];
    const float* asq1 = (const float*)d_in[base + 1];
    const float* adq1 = (const float*)d_in[base + 2];
    const float* bq1  = (const float*)d_in[base + 3];
    const float* Wq2  = (const float*)d_in[base + 4];
    const float* asq2 = (const float*)d_in[base + 5];
    const float* adq2 = (const float*)d_in[base + 6];
    const float* bq2  = (const float*)d_in[base + 7];
    const float* Wk1  = (const float*)d_in[base + 8];
    const float* ask1 = (const float*)d_in[base + 9];
    const float* adk1 = (const float*)d_in[base + 10];
    const float* bk1  = (const float*)d_in[base + 11];
    const float* Wk2  = (const float*)d_in[base + 12];
    const float* ask2 = (const float*)d_in[base + 13];
    const float* adk2 = (const float*)d_in[base + 14];
    const float* bk2  = (const float*)d_in[base + 15];
    const float* queue= (const float*)d_in[base + 16];

    int G = in_sizes[base] / F512;
    int N = in_sizes[0] / G;
    int E = in_sizes[2] / 2;
    int R = in_sizes[base + 16] / C128;
    int B = (out_size % (R + 2) == 0) ? out_size / (R + 2) : out_size / (R + 1);
    if (B > N) B = N;
    int ET = E + N;
    int Mp = (N + BM - 1) / BM * BM;
    if (Mp > MPAD) Mp = MPAD;
    int Kp1 = (G + 63) & ~63;

    float *Hbuf, *asrc, *adst, *seedq, *seedk, *aggr2;
    float *ask1m, *adk1m, *bk1m, *ask2m, *adk2m, *bk2m;
    int *deg, *off, *cur, *csrc;
    hf *A1, *A2, *W1, *W2;
    cudaGetSymbolAddress((void**)&Hbuf, g_H);
    cudaGetSymbolAddress((void**)&asrc, g_asrc);
    cudaGetSymbolAddress((void**)&adst, g_adst);
    cudaGetSymbolAddress((void**)&seedq, g_seedq);
    cudaGetSymbolAddress((void**)&seedk, g_seedk);
    cudaGetSymbolAddress((void**)&aggr2, g_aggr2);
    cudaGetSymbolAddress((void**)&ask1m, g_ask1m);
    cudaGetSymbolAddress((void**)&adk1m, g_adk1m);
    cudaGetSymbolAddress((void**)&bk1m, g_bk1m);
    cudaGetSymbolAddress((void**)&ask2m, g_ask2m);
    cudaGetSymbolAddress((void**)&adk2m, g_adk2m);
    cudaGetSymbolAddress((void**)&bk2m, g_bk2m);
    cudaGetSymbolAddress((void**)&deg, g_deg);
    cudaGetSymbolAddress((void**)&off, g_off);
    cudaGetSymbolAddress((void**)&cur, g_cur);
    cudaGetSymbolAddress((void**)&csrc, g_csrc);
    cudaGetSymbolAddress((void**)&A1, g_A1);
    cudaGetSymbolAddress((void**)&A2, g_A2);
    cudaGetSymbolAddress((void**)&W1, g_W1);
    cudaGetSymbolAddress((void**)&W2, g_W2);

    cudaFuncSetAttribute(gemm_wmma_fp16_kernel,
                         cudaFuncAttributeMaxDynamicSharedMemorySize, SMEM_GEMM_BYTES);

    const size_t a1slot = (size_t)Mp * Kp1;
    const size_t a2slot = (size_t)MPAD * F512;
    const size_t hslot  = (size_t)MPAD * F512;
    const size_t w1slot = (size_t)Kp1 * F512;
    const size_t w2slot = (size_t)F512 * F512;
    const size_t aggr2slot = (size_t)NMAX * F512 / 4;
    hf* Hh = A1;   // fp16 H copy aliases A1 (A1 dead after layer-1 GEMM)

    long totA1 = (long)Mp * Kp1;
    long wtot = 2 * (long)w1slot + 2 * (long)w2slot;
    long h4 = (long)(2 * hslot) / 4;

    // 1) input convert (batched q/k)
    conv_pad2_kernel<<<dim3((unsigned)((totA1 + 255) / 256), 2), 256>>>(
        im_q, im_k, N, G, Kp1, totA1, A1);
    // 2) all weight converts (+momentum blend for key)
    wconv_all_kernel<<<(int)((wtot + 255) / 256), 256>>>(
        Wq1, Wk1, Wq2, Wk2, G, Kp1, W1, W2);
    // 3) misc prep
    misc_prep_kernel<<<(2 * N + 2688 + 255) / 256, 256>>>(
        N, deg, cur,
        ask1, asq1, adk1, adq1, bk1, bq1,
        ask2, asq2, adk2, adq2, bk2, bq2,
        ask1m, adk1m, bk1m, ask2m, adk2m, bk2m);
    // 4) layer-1 GEMM (batched) -- ncu capture target
    {
        dim3 grid(F512 / BN, Mp / BM, 2);
        gemm_wmma_fp16_kernel<<<grid, TGEMM, SMEM_GEMM_BYTES>>>(
            Kp1, F512, A1, W1, Hbuf, a1slot, w1slot, hslot);
    }
    // 5-7) CSR
    csr_count_kernel<<<(ET + 255) / 256, 256>>>(ei, E, N, deg);
    csr_scan_kernel<<<1, 1024>>>(deg, off, N);
    csr_fill_kernel<<<(ET + 255) / 256, 256>>>(ei, E, N, off, cur, csrc);
    // 8) convert H -> fp16 (overwrites A1, which is now dead)
    f2h_kernel<<<(int)((h4 + 255) / 256), 256>>>(Hbuf, Hh, h4);
    // 9-10) layer-1 attention over fp16 H -> fp16 A2
    att_scores_kernel<<<dim3(N, 2), dim3(32, 4)>>>(Hh, hslot, asq1, adq1, ask1m, adk1m,
                                                   asrc, adst, N);
    gat_attn_kernel<<<dim3(N, 2), 256>>>(Hh, hslot, (const float4*)asrc,
                                         (const float4*)adst, off, deg, csrc,
                                         bq1, bk1m, A2, nullptr, 0, a2slot);
    // 11) layer-2 GEMM (batched)
    {
        dim3 grid(F512 / BN, Mp / BM, 2);
        gemm_wmma_fp16_kernel<<<grid, TGEMM, SMEM_GEMM_BYTES>>>(
            F512, F512, A2, W2, Hbuf, a2slot, w2slot, hslot);
    }
    // 12) convert H -> fp16
    f2h_kernel<<<(int)((h4 + 255) / 256), 256>>>(Hbuf, Hh, h4);
    // 13-14) layer-2 attention (dst < B only), fp32 out
    att_scores_kernel<<<dim3(N, 2), dim3(32, 4)>>>(Hh, hslot, asq2, adq2, ask2m, adk2m,
                                                   asrc, adst, N);
    gat_attn_kernel<<<dim3(B, 2), 256>>>(Hh, hslot, (const float4*)asrc,
                                         (const float4*)adst, off, deg, csrc,
                                         nullptr, nullptr, nullptr,
                                         aggr2, aggr2slot, 0);
    // 15) head-mean + l2norm
    head_mean_norm_kernel<<<dim3(B, 2), 128>>>(aggr2, aggr2slot, bq2, bk2m,
                                               seedq, seedk, B);
    // 16) logits
    {
        long written = (long)B * (R + 1);
        long tail = (long)out_size - written;
        if (tail < 0) tail = 0;
        dim3 grid((R + LT - 1) / LT, (B + LT - 1) / LT);
        logits_gemm_kernel<<<grid, 256>>>(seedq, seedk, queue, (float*)d_out,
                                          B, R, written, tail);
    }
}

// round 15
// speedup vs baseline: 1.0509x; 1.0509x over previous
#include <cuda_runtime.h>
#include <cuda_fp16.h>
#include <mma.h>
#include <cstdint>

using namespace nvcuda;

// ---------------------------------------------------------------------------
// MoCoGraph: two 2-layer GAT encoders + MoCo logits.
// GEMMs: fp16 single-pass wmma (fp32 accum), CTA 192x128, 8 warps,
//        warp tile 48x64, BK=64 cp.async double-buffer, 2 CTAs/SM, fp32 out.
// Attention: CSR gather over fp32 H, phase-C 4-way unrolled (MLP=4).
// Logits: smem-tiled fp32 GEMM.
// ---------------------------------------------------------------------------

#define NMAX   10240
#define MPAD   10368     // multiple of 192 >= N
#define ETMAX  180224
#define F512   512
#define C128   128
#define CAP    512
#define KPAD1  1024

typedef __half hf;

// ------------------------- device scratch (no mallocs) ---------------------
__device__ float g_H  [2 * (size_t)MPAD * F512];
__device__ hf    g_A1 [2 * (size_t)MPAD * KPAD1];
__device__ hf    g_A2 [2 * (size_t)MPAD * F512];   // pad rows stay 0 (zero-init)
__device__ hf    g_W1 [2 * KPAD1 * F512];
__device__ hf    g_W2 [2 * F512 * F512];
__device__ float g_asrc[2 * NMAX * 4];
__device__ float g_adst[2 * NMAX * 4];
__device__ float g_seedq[(size_t)NMAX * C128];
__device__ float g_seedk[(size_t)NMAX * C128];
__device__ float g_ask1m[F512], g_adk1m[F512], g_bk1m[F512];
__device__ float g_ask2m[F512], g_adk2m[F512], g_bk2m[C128];
__device__ int g_deg[NMAX];
__device__ int g_off[NMAX + 1];
__device__ int g_cur[NMAX];
__device__ int g_csrc[ETMAX];
__device__ float g_aggr2[2 * (size_t)NMAX * F512 / 4];   // layer-2 fp32 out (B rows)

// ------------------------------ helpers ------------------------------------
__device__ __forceinline__ uint32_t smem_u32(const void* p) {
    uint32_t a;
    asm("{ .reg .u64 t; cvta.to.shared.u64 t, %1; cvt.u32.u64 %0, t; }" : "=r"(a) : "l"(p));
    return a;
}
__device__ __forceinline__ void cp_async16(uint32_t s, const void* g) {
    asm volatile("cp.async.cg.shared.global [%0], [%1], 16;" :: "r"(s), "l"(g));
}
#define CP_COMMIT() asm volatile("cp.async.commit_group;" ::: "memory")
#define CP_WAIT(n)  asm volatile("cp.async.wait_group %0;" :: "n"(n) : "memory")

// ------------------------------ prep kernels -------------------------------
__global__ void conv_pad2_kernel(const float* __restrict__ in0,
                                 const float* __restrict__ in1,
                                 int M, int K, int Kp, long total,
                                 hf* __restrict__ out) {
    long idx = (long)blockIdx.x * blockDim.x + threadIdx.x;
    if (idx >= total) return;
    const float* in = blockIdx.y ? in1 : in0;
    size_t o = (size_t)blockIdx.y * total + idx;
    int r = (int)(idx / Kp), c = (int)(idx % Kp);
    float v = (r < M && c < K) ? in[(size_t)r * K + c] : 0.f;
    out[o] = __float2half_rn(v);
}

__global__ void wconv_all_kernel(const float* __restrict__ Wq1,
                                 const float* __restrict__ Wk1,
                                 const float* __restrict__ Wq2,
                                 const float* __restrict__ Wk2,
                                 int G, int Kp1,
                                 hf* __restrict__ W1, hf* __restrict__ W2) {
    long idx = (long)blockIdx.x * blockDim.x + threadIdx.x;
    const long s1 = (long)Kp1 * F512;
    const long s2 = (long)F512 * F512;
    if (idx < 2 * s1) {
        int z = idx >= s1;
        long j = idx - (long)z * s1;
        int r = (int)(j / F512);
        float v = 0.f;
        if (r < G) v = z ? (0.99f * Wk1[j] + 0.01f * Wq1[j]) : Wq1[j];
        W1[idx] = __float2half_rn(v);
    } else if (idx < 2 * s1 + 2 * s2) {
        long j2 = idx - 2 * s1;
        int z = j2 >= s2;
        long j = j2 - (long)z * s2;
        float v = z ? (0.99f * Wk2[j] + 0.01f * Wq2[j]) : Wq2[j];
        W2[j2] = __float2half_rn(v);
    }
}

__global__ void misc_prep_kernel(int N,
                                 int* __restrict__ deg, int* __restrict__ cur,
                                 const float* ask1, const float* asq1,
                                 const float* adk1, const float* adq1,
                                 const float* bk1,  const float* bq1,
                                 const float* ask2, const float* asq2,
                                 const float* adk2, const float* adq2,
                                 const float* bk2,  const float* bq2,
                                 float* o1, float* o2, float* o3,
                                 float* o4, float* o5, float* o6) {
    int idx = blockIdx.x * blockDim.x + threadIdx.x;
    if (idx < N) { deg[idx] = 0; return; }
    if (idx < 2 * N) { cur[idx - N] = 0; return; }
    int j = idx - 2 * N;
    if (j < 512)       o1[j]        = 0.99f * ask1[j]        + 0.01f * asq1[j];
    else if (j < 1024) o2[j - 512]  = 0.99f * adk1[j - 512]  + 0.01f * adq1[j - 512];
    else if (j < 1536) o3[j - 1024] = 0.99f * bk1[j - 1024]  + 0.01f * bq1[j - 1024];
    else if (j < 2048) o4[j - 1536] = 0.99f * ask2[j - 1536] + 0.01f * asq2[j - 1536];
    else if (j < 2560) o5[j - 2048] = 0.99f * adk2[j - 2048] + 0.01f * adq2[j - 2048];
    else if (j < 2688) o6[j - 2560] = 0.99f * bk2[j - 2560]  + 0.01f * bq2[j - 2560];
}

// ------------------------------- CSR build ---------------------------------
__global__ void csr_count_kernel(const int* __restrict__ ei, int E, int N,
                                 int* __restrict__ deg) {
    int i = blockIdx.x * blockDim.x + threadIdx.x;
    int ET = E + N;
    if (i >= ET) return;
    int d = (i < E) ? ei[E + i] : (i - E);
    atomicAdd(&deg[d], 1);
}

__global__ void csr_scan_kernel(const int* __restrict__ deg,
                                int* __restrict__ off, int N) {
    __shared__ int sh[1024];
    __shared__ int carry;
    int t = threadIdx.x;
    if (t == 0) carry = 0;
    __syncthreads();
    for (int base = 0; base < N; base += 1024) {
        int v = (base + t < N) ? deg[base + t] : 0;
        sh[t] = v;
        __syncthreads();
        for (int o = 1; o < 1024; o <<= 1) {
            int x = (t >= o) ? sh[t - o] : 0;
            __syncthreads();
            sh[t] += x;
            __syncthreads();
        }
        int excl = sh[t] - v + carry;
        if (base + t < N) off[base + t] = excl;
        __syncthreads();
        if (t == 1023) carry += sh[1023];
        __syncthreads();
    }
    if (t == 0) off[N] = carry;
}

__global__ void csr_fill_kernel(const int* __restrict__ ei, int E, int N,
                                const int* __restrict__ off,
                                int* __restrict__ cur,
                                int* __restrict__ csrc) {
    int i = blockIdx.x * blockDim.x + threadIdx.x;
    int ET = E + N;
    if (i >= ET) return;
    int s, d;
    if (i < E) { s = ei[i]; d = ei[E + i]; } else { s = d = i - E; }
    int pos = atomicAdd(&cur[d], 1);
    csrc[off[d] + pos] = s;
}

// ------ batched fp16 wmma GEMM: CTA 192x128, 8 warps, warp 48x64, BK=64 ----
#define BM 192
#define BN 128
#define BK 64
#define TGEMM 256
#define A_LD 72
#define B_LD 136
#define A_TILE_B 27648u
#define B_TILE_B 17408u
#define ST_A 0u
#define ST_B A_TILE_B
#define STAGE_B (A_TILE_B + B_TILE_B)   // 45056
#define SMEM_GEMM_BYTES (2 * STAGE_B)   // 90112 -> 2 CTAs/SM

__global__ void __launch_bounds__(TGEMM, 2)
gemm_wmma_fp16_kernel(int K, int Nn,
                      const hf* __restrict__ Ag0, const hf* __restrict__ Bg0,
                      float* __restrict__ C0,
                      size_t strideA, size_t strideB, size_t strideC) {
    extern __shared__ char smem[];
    const uint32_t sb = smem_u32(smem);
    const int tid = threadIdx.x;
    const int bn = blockIdx.x, bm = blockIdx.y;
    const size_t z = blockIdx.z;
    const hf* Ag = Ag0 + z * strideA;
    const hf* Bg = Bg0 + z * strideB;
    float* C = C0 + z * strideC;

    const int warpId = tid >> 5;
    const int wm = warpId & 3;
    const int wn = warpId >> 2;
    const int nk = K >> 6;

    const size_t aBase = (size_t)(bm * BM);
    const int cCol = bn * BN;

    auto load_stage = [&](int kt, uint32_t stg) {
#pragma unroll
        for (int i = 0; i < 6; i++) {
            int idx = tid + (i << 8);
            int ar = idx >> 3, as = (idx & 7) << 3;
            cp_async16(sb + stg + ST_A + (uint32_t)(ar * A_LD + as) * 2,
                       Ag + (aBase + ar) * K + kt * BK + as);
        }
#pragma unroll
        for (int i = 0; i < 4; i++) {
            int idx = tid + (i << 8);
            int br = idx >> 4, bs = (idx & 15) << 3;
            cp_async16(sb + stg + ST_B + (uint32_t)(br * B_LD + bs) * 2,
                       Bg + (size_t)(kt * BK + br) * Nn + cCol + bs);
        }
        CP_COMMIT();
    };

    wmma::fragment<wmma::accumulator, 16, 16, 16, float> acc[3][4];
#pragma unroll
    for (int i = 0; i < 3; i++)
#pragma unroll
        for (int j = 0; j < 4; j++) wmma::fill_fragment(acc[i][j], 0.0f);

    load_stage(0, 0);

    for (int kt = 0; kt < nk; kt++) {
        const uint32_t stg = (kt & 1) ? STAGE_B : 0u;
        if (kt + 1 < nk) {
            load_stage(kt + 1, (kt & 1) ? 0u : STAGE_B);
            CP_WAIT(1);
        } else {
            CP_WAIT(0);
        }
        __syncthreads();

        const hf* sA = (const hf*)(smem + stg + ST_A);
        const hf* sB = (const hf*)(smem + stg + ST_B);

#pragma unroll
        for (int kk = 0; kk < BK; kk += 16) {
            wmma::fragment<wmma::matrix_a, 16, 16, 16, hf, wmma::row_major> af[3];
#pragma unroll
            for (int i = 0; i < 3; i++)
                wmma::load_matrix_sync(af[i], sA + (wm * 48 + i * 16) * A_LD + kk, A_LD);
#pragma unroll
            for (int j = 0; j < 4; j++) {
                wmma::fragment<wmma::matrix_b, 16, 16, 16, hf, wmma::row_major> bf;
                wmma::load_matrix_sync(bf, sB + kk * B_LD + wn * 64 + j * 16, B_LD);
#pragma unroll
                for (int i = 0; i < 3; i++)
                    wmma::mma_sync(acc[i][j], af[i], bf, acc[i][j]);
            }
        }
        __syncthreads();
    }

#pragma unroll
    for (int i = 0; i < 3; i++) {
        int row = bm * BM + wm * 48 + i * 16;
#pragma unroll
        for (int j = 0; j < 4; j++) {
            int col = cCol + wn * 64 + j * 16;
            wmma::store_matrix_sync(&C[(size_t)row * Nn + col], acc[i][j],
                                    Nn, wmma::mem_row_major);
        }
    }
}

// ---------------------------- attention scores (batched) -------------------
__global__ void att_scores_kernel(const float* __restrict__ Hbase, size_t hstride,
                                  const float* __restrict__ s0, const float* __restrict__ d0,
                                  const float* __restrict__ s1, const float* __restrict__ d1,
                                  float* __restrict__ a_s_base,
                                  float* __restrict__ a_d_base, int N) {
    int n = blockIdx.x;
    if (n >= N) return;
    int z = blockIdx.y;
    const float* Hf = Hbase + (size_t)z * hstride;
    const float* att_s = z ? s1 : s0;
    const float* att_d = z ? d1 : d0;
    float* a_s = a_s_base + (size_t)z * NMAX * 4;
    float* a_d = a_d_base + (size_t)z * NMAX * 4;

    int h = threadIdx.y;
    int lane = threadIdx.x;
    const float* row = Hf + (size_t)n * F512 + h * C128;
    float ss = 0.f, sd = 0.f;
#pragma unroll
    for (int j = 0; j < 4; j++) {
        int c = lane + 32 * j;
        float v = row[c];
        ss += v * att_s[h * C128 + c];
        sd += v * att_d[h * C128 + c];
    }
#pragma unroll
    for (int o = 16; o > 0; o >>= 1) {
        ss += __shfl_down_sync(0xffffffffu, ss, o);
        sd += __shfl_down_sync(0xffffffffu, sd, o);
    }
    if (lane == 0) { a_s[n * 4 + h] = ss; a_d[n * 4 + h] = sd; }
}

// ---------------- fused per-dst softmax + aggregation (batched) ------------
__device__ __forceinline__ float leaky(float e) { return e > 0.f ? e : 0.2f * e; }

__global__ __launch_bounds__(256)
void gat_attn_kernel(const float* __restrict__ Hbase, size_t hstride,
                     const float4* __restrict__ a_s_base,
                     const float4* __restrict__ a_d_base,
                     const int* __restrict__ off,
                     const int* __restrict__ deg_arr,
                     const int* __restrict__ csrc,
                     const float* __restrict__ bias0,
                     const float* __restrict__ bias1,
                     hf* __restrict__ outh,
                     float* __restrict__ outf, size_t ostride,
                     size_t oslot) {
    int d = blockIdx.x;
    int z = blockIdx.y;
    int t = threadIdx.x;
    int lane = t & 31, wid = t >> 5;

    const float* Hf = Hbase + (size_t)z * hstride;
    const float4* a_s4 = a_s_base + (size_t)z * NMAX;
    const float4* a_d4 = a_d_base + (size_t)z * NMAX;
    const float* bias = z ? bias1 : bias0;

    __shared__ int   s_list[CAP];
    __shared__ float w[CAP][4];
    __shared__ float red[8][4];
    __shared__ float mx_s[4], invd_s[4];

    const int start = off[d];
    const int deg = deg_arr[d];
    const float4 ad = a_d4[d];

    float m0 = -1e30f, m1 = -1e30f, m2 = -1e30f, m3 = -1e30f;
    for (int j = t; j < deg; j += 256) {
        int s = csrc[start + j];
        float4 as = a_s4[s];
        float e0 = leaky(as.x + ad.x);
        float e1 = leaky(as.y + ad.y);
        float e2 = leaky(as.z + ad.z);
        float e3 = leaky(as.w + ad.w);
        if (j < CAP) {
            s_list[j] = s;
            w[j][0] = e0; w[j][1] = e1; w[j][2] = e2; w[j][3] = e3;
        }
        m0 = fmaxf(m0, e0); m1 = fmaxf(m1, e1);
        m2 = fmaxf(m2, e2); m3 = fmaxf(m3, e3);
    }
#pragma unroll
    for (int o = 16; o > 0; o >>= 1) {
        m0 = fmaxf(m0, __shfl_xor_sync(0xffffffffu, m0, o));
        m1 = fmaxf(m1, __shfl_xor_sync(0xffffffffu, m1, o));
        m2 = fmaxf(m2, __shfl_xor_sync(0xffffffffu, m2, o));
        m3 = fmaxf(m3, __shfl_xor_sync(0xffffffffu, m3, o));
    }
    if (lane == 0) { red[wid][0] = m0; red[wid][1] = m1; red[wid][2] = m2; red[wid][3] = m3; }
    __syncthreads();
    if (t < 4) {
        float mm = -1e30f;
#pragma unroll
        for (int k = 0; k < 8; k++) mm = fmaxf(mm, red[k][t]);
        mx_s[t] = mm;
    }
    __syncthreads();
    const float mx0 = mx_s[0], mx1 = mx_s[1], mx2 = mx_s[2], mx3 = mx_s[3];

    float s0 = 0.f, s1 = 0.f, s2 = 0.f, s3 = 0.f;
    for (int j = t; j < deg; j += 256) {
        float e0, e1, e2, e3;
        if (j < CAP) {
            e0 = w[j][0]; e1 = w[j][1]; e2 = w[j][2]; e3 = w[j][3];
        } else {
            int s = csrc[start + j];
            float4 as = a_s4[s];
            e0 = leaky(as.x + ad.x); e1 = leaky(as.y + ad.y);
            e2 = leaky(as.z + ad.z); e3 = leaky(as.w + ad.w);
        }
        float x0 = expf(e0 - mx0), x1 = expf(e1 - mx1);
        float x2 = expf(e2 - mx2), x3 = expf(e3 - mx3);
        if (j < CAP) { w[j][0] = x0; w[j][1] = x1; w[j][2] = x2; w[j][3] = x3; }
        s0 += x0; s1 += x1; s2 += x2; s3 += x3;
    }
#pragma unroll
    for (int o = 16; o > 0; o >>= 1) {
        s0 += __shfl_xor_sync(0xffffffffu, s0, o);
        s1 += __shfl_xor_sync(0xffffffffu, s1, o);
        s2 += __shfl_xor_sync(0xffffffffu, s2, o);
        s3 += __shfl_xor_sync(0xffffffffu, s3, o);
    }
    __syncthreads();
    if (lane == 0) { red[wid][0] = s0; red[wid][1] = s1; red[wid][2] = s2; red[wid][3] = s3; }
    __syncthreads();
    if (t < 4) {
        float ssum = 0.f;
#pragma unroll
        for (int k = 0; k < 8; k++) ssum += red[k][t];
        invd_s[t] = 1.0f / (ssum + 1e-16f);
    }
    __syncthreads();

    // ---- phase C: 4-way unrolled weighted gather (MLP=4) ----
    const int c2 = t * 2;
    const int h = c2 >> 7;
    const float inv = invd_s[h];
    const float mxh = mx_s[h];
    float acc0 = 0.f, acc1 = 0.f;
    const int mdeg = (deg < CAP) ? deg : CAP;
    int j = 0;
    for (; j + 4 <= mdeg; j += 4) {
        int sA = s_list[j],     sB = s_list[j + 1];
        int sC = s_list[j + 2], sD = s_list[j + 3];
        float wA = w[j][h],     wB = w[j + 1][h];
        float wC = w[j + 2][h], wD = w[j + 3][h];
        float2 vA = *(const float2*)(Hf + (size_t)sA * F512 + c2);
        float2 vB = *(const float2*)(Hf + (size_t)sB * F512 + c2);
        float2 vC = *(const float2*)(Hf + (size_t)sC * F512 + c2);
        float2 vD = *(const float2*)(Hf + (size_t)sD * F512 + c2);
        float aA = wA * inv, aB = wB * inv, aC = wC * inv, aD = wD * inv;
        acc0 += vA.x * aA + vB.x * aB + vC.x * aC + vD.x * aD;
        acc1 += vA.y * aA + vB.y * aB + vC.y * aC + vD.y * aD;
    }
    for (; j < mdeg; j++) {
        int s = s_list[j];
        float alpha = w[j][h] * inv;
        float2 v = *(const float2*)(Hf + (size_t)s * F512 + c2);
        acc0 += v.x * alpha;
        acc1 += v.y * alpha;
    }
    for (; j < deg; j++) {   // spill path (deg > CAP)
        int s = csrc[start + j];
        const float* asp = (const float*)&a_s4[s];
        const float* adp = (const float*)&ad;
        float ww = expf(leaky(asp[h] + adp[h]) - mxh);
        float alpha = ww * inv;
        float2 v = *(const float2*)(Hf + (size_t)s * F512 + c2);
        acc0 += v.x * alpha;
        acc1 += v.y * alpha;
    }
    if (outh) {
        acc0 = fmaxf(acc0 + bias[c2], 0.f);
        acc1 = fmaxf(acc1 + bias[c2 + 1], 0.f);
        size_t o = (size_t)z * oslot + (size_t)d * F512 + c2;
        *(__half2*)(outh + o) = __floats2half2_rn(acc0, acc1);
    } else {
        size_t o = (size_t)z * ostride + (size_t)d * F512 + c2;
        *(float2*)(outf + o) = make_float2(acc0, acc1);
    }
}

// layer-2 epilogue (batched)
__global__ void head_mean_norm_kernel(const float* __restrict__ aggr_base, size_t astride,
                                      const float* __restrict__ bias0,
                                      const float* __restrict__ bias1,
                                      float* __restrict__ outq,
                                      float* __restrict__ outk, int B) {
    int n = blockIdx.x;
    if (n >= B) return;
    int z = blockIdx.y;
    const float* aggr = aggr_base + (size_t)z * astride;
    const float* bias = z ? bias1 : bias0;
    float* outv = z ? outk : outq;
    int c = threadIdx.x;
    size_t base = (size_t)n * F512;
    float v = 0.25f * (aggr[base + c] + aggr[base + 128 + c] +
                       aggr[base + 256 + c] + aggr[base + 384 + c]) + bias[c];
    float s = v * v;
#pragma unroll
    for (int o = 16; o > 0; o >>= 1) s += __shfl_down_sync(0xffffffffu, s, o);
    __shared__ float red[4];
    if ((c & 31) == 0) red[c >> 5] = s;
    __syncthreads();
    float tot = red[0] + red[1] + red[2] + red[3];
    outv[(size_t)n * C128 + c] = v * rsqrtf(tot + 1e-24f);
}

// ---------------- logits: tiled fp32 GEMM out[B,1+R] ------------------------
#define LT 64
__global__ __launch_bounds__(256)
void logits_gemm_kernel(const float* __restrict__ q,
                        const float* __restrict__ kv,
                        const float* __restrict__ queue,
                        float* __restrict__ out, int B, int R,
                        long tail_off, long tail_len) {
    __shared__ float qt[LT][33];
    __shared__ float kt[32][LT + 4];
    const int tid = threadIdx.x;
    const int bx = blockIdx.x, by = blockIdx.y;
    const int tx = tid & 15, ty = tid >> 4;

    float acc[4][4];
#pragma unroll
    for (int i = 0; i < 4; i++)
#pragma unroll
        for (int j = 0; j < 4; j++) acc[i][j] = 0.f;

    for (int k0 = 0; k0 < 128; k0 += 32) {
#pragma unroll
        for (int i = 0; i < 8; i++) {
            int e = tid + i * 256;
            int r = e >> 5, c = e & 31;
            int gr = by * LT + r;
            qt[r][c] = (gr < B) ? q[(size_t)gr * 128 + k0 + c] : 0.f;
        }
#pragma unroll
        for (int i = 0; i < 8; i++) {
            int e = tid + i * 256;
            int r = e >> 6, c = e & 63;
            int gc = bx * LT + c;
            kt[r][c] = (gc < R) ? queue[(size_t)(k0 + r) * R + gc] : 0.f;
        }
        __syncthreads();
#pragma unroll
        for (int k = 0; k < 32; k++) {
            float ra[4], rb[4];
#pragma unroll
            for (int i = 0; i < 4; i++) ra[i] = qt[ty * 4 + i][k];
#pragma unroll
            for (int j = 0; j < 4; j++) rb[j] = kt[k][tx * 4 + j];
#pragma unroll
            for (int i = 0; i < 4; i++)
#pragma unroll
                for (int j = 0; j < 4; j++) acc[i][j] += ra[i] * rb[j];
        }
        __syncthreads();
    }

#pragma unroll
    for (int i = 0; i < 4; i++) {
        int row = by * LT + ty * 4 + i;
        if (row >= B) continue;
#pragma unroll
        for (int j = 0; j < 4; j++) {
            int col = bx * LT + tx * 4 + j;
            if (col < R)
                out[(size_t)row * (R + 1) + 1 + col] = acc[i][j] * 5.0f;
        }
    }

    if (bx == 0 && tid < LT) {
        int n = by * LT + tid;
        if (n < B) {
            const float* qr = q + (size_t)n * 128;
            const float* kr = kv + (size_t)n * 128;
            float s = 0.f;
#pragma unroll 4
            for (int c = 0; c < 128; c++) s += qr[c] * kr[c];
            out[(size_t)n * (R + 1)] = s * 5.0f;
        }
    }
    if (bx == 0 && by == 0) {
        for (long i = tid; i < tail_len; i += 256) out[tail_off + i] = 0.f;
    }
}

// ------------------------------- launch ------------------------------------
extern "C" void kernel_launch(void* const* d_in, const int* in_sizes, int n_in,
                              void* d_out, int out_size) {
    int base = n_in - 17;

    const float* im_q = (const float*)d_in[0];
    const float* im_k = (const float*)d_in[1];
    const int*   ei   = (const int*)d_in[2];

    const float* Wq1  = (const float*)d_in[base + 0];
    const float* asq1 = (const float*)d_in[base + 1];
    const float* adq1 = (const float*)d_in[base + 2];
    const float* bq1  = (const float*)d_in[base + 3];
    const float* Wq2  = (const float*)d_in[base + 4];
    const float* asq2 = (const float*)d_in[base + 5];
    const float* adq2 = (const float*)d_in[base + 6];
    const float* bq2  = (const float*)d_in[base + 7];
    const float* Wk1  = (const float*)d_in[base + 8];
    const float* ask1 = (const float*)d_in[base + 9];
    const float* adk1 = (const float*)d_in[base + 10];
    const float* bk1  = (const float*)d_in[base + 11];
    const float* Wk2  = (const float*)d_in[base + 12];
    const float* ask2 = (const float*)d_in[base + 13];
    const float* adk2 = (const float*)d_in[base + 14];
    const float* bk2  = (const float*)d_in[base + 15];
    const float* queue= (const float*)d_in[base + 16];

    int G = in_sizes[base] / F512;
    int N = in_sizes[0] / G;
    int E = in_sizes[2] / 2;
    int R = in_sizes[base + 16] / C128;
    int B = (out_size % (R + 2) == 0) ? out_size / (R + 2) : out_size / (R + 1);
    if (B > N) B = N;
    int ET = E + N;
    int Mp = (N + BM - 1) / BM * BM;
    if (Mp > MPAD) Mp = MPAD;
    int Kp1 = (G + 63) & ~63;

    float *Hbuf, *asrc, *adst, *seedq, *seedk, *aggr2;
    float *ask1m, *adk1m, *bk1m, *ask2m, *adk2m, *bk2m;
    int *deg, *off, *cur, *csrc;
    hf *A1, *A2, *W1, *W2;
    cudaGetSymbolAddress((void**)&Hbuf, g_H);
    cudaGetSymbolAddress((void**)&asrc, g_asrc);
    cudaGetSymbolAddress((void**)&adst, g_adst);
    cudaGetSymbolAddress((void**)&seedq, g_seedq);
    cudaGetSymbolAddress((void**)&seedk, g_seedk);
    cudaGetSymbolAddress((void**)&aggr2, g_aggr2);
    cudaGetSymbolAddress((void**)&ask1m, g_ask1m);
    cudaGetSymbolAddress((void**)&adk1m, g_adk1m);
    cudaGetSymbolAddress((void**)&bk1m, g_bk1m);
    cudaGetSymbolAddress((void**)&ask2m, g_ask2m);
    cudaGetSymbolAddress((void**)&adk2m, g_adk2m);
    cudaGetSymbolAddress((void**)&bk2m, g_bk2m);
    cudaGetSymbolAddress((void**)&deg, g_deg);
    cudaGetSymbolAddress((void**)&off, g_off);
    cudaGetSymbolAddress((void**)&cur, g_cur);
    cudaGetSymbolAddress((void**)&csrc, g_csrc);
    cudaGetSymbolAddress((void**)&A1, g_A1);
    cudaGetSymbolAddress((void**)&A2, g_A2);
    cudaGetSymbolAddress((void**)&W1, g_W1);
    cudaGetSymbolAddress((void**)&W2, g_W2);

    cudaFuncSetAttribute(gemm_wmma_fp16_kernel,
                         cudaFuncAttributeMaxDynamicSharedMemorySize, SMEM_GEMM_BYTES);

    const size_t a1slot = (size_t)Mp * Kp1;
    const size_t a2slot = (size_t)MPAD * F512;
    const size_t hslot  = (size_t)MPAD * F512;
    const size_t w1slot = (size_t)Kp1 * F512;
    const size_t w2slot = (size_t)F512 * F512;
    const size_t aggr2slot = (size_t)NMAX * F512 / 4;   // >= B*512

    long totA1 = (long)Mp * Kp1;
    long wtot = 2 * (long)w1slot + 2 * (long)w2slot;

    // 1) input convert (batched q/k)
    conv_pad2_kernel<<<dim3((unsigned)((totA1 + 255) / 256), 2), 256>>>(
        im_q, im_k, N, G, Kp1, totA1, A1);
    // 2) all weight converts (+momentum blend for key)
    wconv_all_kernel<<<(int)((wtot + 255) / 256), 256>>>(
        Wq1, Wk1, Wq2, Wk2, G, Kp1, W1, W2);
    // 3) misc prep
    misc_prep_kernel<<<(2 * N + 2688 + 255) / 256, 256>>>(
        N, deg, cur,
        ask1, asq1, adk1, adq1, bk1, bq1,
        ask2, asq2, adk2, adq2, bk2, bq2,
        ask1m, adk1m, bk1m, ask2m, adk2m, bk2m);
    // 4) layer-1 GEMM (batched)
    {
        dim3 grid(F512 / BN, Mp / BM, 2);
        gemm_wmma_fp16_kernel<<<grid, TGEMM, SMEM_GEMM_BYTES>>>(
            Kp1, F512, A1, W1, Hbuf, a1slot, w1slot, hslot);
    }
    // 5-7) CSR
    csr_count_kernel<<<(ET + 255) / 256, 256>>>(ei, E, N, deg);
    csr_scan_kernel<<<1, 1024>>>(deg, off, N);
    csr_fill_kernel<<<(ET + 255) / 256, 256>>>(ei, E, N, off, cur, csrc);
    // 8-9) layer-1 attention -> fp16 A2 (pad rows stay zero from init)
    att_scores_kernel<<<dim3(N, 2), dim3(32, 4)>>>(Hbuf, hslot, asq1, adq1, ask1m, adk1m,
                                                   asrc, adst, N);
    gat_attn_kernel<<<dim3(N, 2), 256>>>(Hbuf, hslot, (const float4*)asrc,
                                         (const float4*)adst, off, deg, csrc,
                                         bq1, bk1m, A2, nullptr, 0, a2slot);
    // 10) layer-2 GEMM (batched)
    {
        dim3 grid(F512 / BN, Mp / BM, 2);
        gemm_wmma_fp16_kernel<<<grid, TGEMM, SMEM_GEMM_BYTES>>>(
            F512, F512, A2, W2, Hbuf, a2slot, w2slot, hslot);
    }
    // 11-12) layer-2 attention (dst < B only), fp32 out
    att_scores_kernel<<<dim3(N, 2), dim3(32, 4)>>>(Hbuf, hslot, asq2, adq2, ask2m, adk2m,
                                                   asrc, adst, N);
    gat_attn_kernel<<<dim3(B, 2), 256>>>(Hbuf, hslot, (const float4*)asrc,
                                         (const float4*)adst, off, deg, csrc,
                                         nullptr, nullptr, nullptr,
                                         aggr2, aggr2slot, 0);
    // 13) head-mean + l2norm
    head_mean_norm_kernel<<<dim3(B, 2), 128>>>(aggr2, aggr2slot, bq2, bk2m,
                                               seedq, seedk, B);
    // 14) logits
    {
        long written = (long)B * (R + 1);
        long tail = (long)out_size - written;
        if (tail < 0) tail = 0;
        dim3 grid((R + LT - 1) / LT, (B + LT - 1) / LT);
        logits_gemm_kernel<<<grid, 256>>>(seedq, seedk, queue, (float*)d_out,
                                          B, R, written, tail);
    }
}

// round 16
// speedup vs baseline: 1.0713x; 1.0193x over previous
#include <cuda_runtime.h>
#include <cuda_fp16.h>
#include <mma.h>
#include <cstdint>

using namespace nvcuda;

// ---------------------------------------------------------------------------
// MoCoGraph: two 2-layer GAT encoders + MoCo logits.
// GEMMs: fp16 single-pass wmma (fp32 accum), CTA 144x128 (576 CTAs = 1.95
//        waves at 2 CTAs/SM -> 97% wave util), 6 warps, warp tile 48x64,
//        BK=64 cp.async double-buffer, fp32 out.
// Attention: CSR gather over fp32 H, phase-C 4-way unrolled (MLP=4).
// Logits: smem-tiled fp32 GEMM.
// ---------------------------------------------------------------------------

#define NMAX   10240
#define MPAD   10368     // multiple of 144 (= 144*72) >= N
#define ETMAX  180224
#define F512   512
#define C128   128
#define CAP    512
#define KPAD1  1024

typedef __half hf;

// ------------------------- device scratch (no mallocs) ---------------------
__device__ float g_H  [2 * (size_t)MPAD * F512];
__device__ hf    g_A1 [2 * (size_t)MPAD * KPAD1];
__device__ hf    g_A2 [2 * (size_t)MPAD * F512];   // pad rows stay 0 (zero-init)
__device__ hf    g_W1 [2 * KPAD1 * F512];
__device__ hf    g_W2 [2 * F512 * F512];
__device__ float g_asrc[2 * NMAX * 4];
__device__ float g_adst[2 * NMAX * 4];
__device__ float g_seedq[(size_t)NMAX * C128];
__device__ float g_seedk[(size_t)NMAX * C128];
__device__ float g_ask1m[F512], g_adk1m[F512], g_bk1m[F512];
__device__ float g_ask2m[F512], g_adk2m[F512], g_bk2m[C128];
__device__ int g_deg[NMAX];
__device__ int g_off[NMAX + 1];
__device__ int g_cur[NMAX];
__device__ int g_csrc[ETMAX];
__device__ float g_aggr2[2 * (size_t)NMAX * F512 / 4];   // layer-2 fp32 out (B rows)

// ------------------------------ helpers ------------------------------------
__device__ __forceinline__ uint32_t smem_u32(const void* p) {
    uint32_t a;
    asm("{ .reg .u64 t; cvta.to.shared.u64 t, %1; cvt.u32.u64 %0, t; }" : "=r"(a) : "l"(p));
    return a;
}
__device__ __forceinline__ void cp_async16(uint32_t s, const void* g) {
    asm volatile("cp.async.cg.shared.global [%0], [%1], 16;" :: "r"(s), "l"(g));
}
#define CP_COMMIT() asm volatile("cp.async.commit_group;" ::: "memory")
#define CP_WAIT(n)  asm volatile("cp.async.wait_group %0;" :: "n"(n) : "memory")

// ------------------------------ prep kernels -------------------------------
__global__ void conv_pad2_kernel(const float* __restrict__ in0,
                                 const float* __restrict__ in1,
                                 int M, int K, int Kp, long total,
                                 hf* __restrict__ out) {
    long idx = (long)blockIdx.x * blockDim.x + threadIdx.x;
    if (idx >= total) return;
    const float* in = blockIdx.y ? in1 : in0;
    size_t o = (size_t)blockIdx.y * total + idx;
    int r = (int)(idx / Kp), c = (int)(idx % Kp);
    float v = (r < M && c < K) ? in[(size_t)r * K + c] : 0.f;
    out[o] = __float2half_rn(v);
}

__global__ void wconv_all_kernel(const float* __restrict__ Wq1,
                                 const float* __restrict__ Wk1,
                                 const float* __restrict__ Wq2,
                                 const float* __restrict__ Wk2,
                                 int G, int Kp1,
                                 hf* __restrict__ W1, hf* __restrict__ W2) {
    long idx = (long)blockIdx.x * blockDim.x + threadIdx.x;
    const long s1 = (long)Kp1 * F512;
    const long s2 = (long)F512 * F512;
    if (idx < 2 * s1) {
        int z = idx >= s1;
        long j = idx - (long)z * s1;
        int r = (int)(j / F512);
        float v = 0.f;
        if (r < G) v = z ? (0.99f * Wk1[j] + 0.01f * Wq1[j]) : Wq1[j];
        W1[idx] = __float2half_rn(v);
    } else if (idx < 2 * s1 + 2 * s2) {
        long j2 = idx - 2 * s1;
        int z = j2 >= s2;
        long j = j2 - (long)z * s2;
        float v = z ? (0.99f * Wk2[j] + 0.01f * Wq2[j]) : Wq2[j];
        W2[j2] = __float2half_rn(v);
    }
}

__global__ void misc_prep_kernel(int N,
                                 int* __restrict__ deg, int* __restrict__ cur,
                                 const float* ask1, const float* asq1,
                                 const float* adk1, const float* adq1,
                                 const float* bk1,  const float* bq1,
                                 const float* ask2, const float* asq2,
                                 const float* adk2, const float* adq2,
                                 const float* bk2,  const float* bq2,
                                 float* o1, float* o2, float* o3,
                                 float* o4, float* o5, float* o6) {
    int idx = blockIdx.x * blockDim.x + threadIdx.x;
    if (idx < N) { deg[idx] = 0; return; }
    if (idx < 2 * N) { cur[idx - N] = 0; return; }
    int j = idx - 2 * N;
    if (j < 512)       o1[j]        = 0.99f * ask1[j]        + 0.01f * asq1[j];
    else if (j < 1024) o2[j - 512]  = 0.99f * adk1[j - 512]  + 0.01f * adq1[j - 512];
    else if (j < 1536) o3[j - 1024] = 0.99f * bk1[j - 1024]  + 0.01f * bq1[j - 1024];
    else if (j < 2048) o4[j - 1536] = 0.99f * ask2[j - 1536] + 0.01f * asq2[j - 1536];
    else if (j < 2560) o5[j - 2048] = 0.99f * adk2[j - 2048] + 0.01f * adq2[j - 2048];
    else if (j < 2688) o6[j - 2560] = 0.99f * bk2[j - 2560]  + 0.01f * bq2[j - 2560];
}

// ------------------------------- CSR build ---------------------------------
__global__ void csr_count_kernel(const int* __restrict__ ei, int E, int N,
                                 int* __restrict__ deg) {
    int i = blockIdx.x * blockDim.x + threadIdx.x;
    int ET = E + N;
    if (i >= ET) return;
    int d = (i < E) ? ei[E + i] : (i - E);
    atomicAdd(&deg[d], 1);
}

__global__ void csr_scan_kernel(const int* __restrict__ deg,
                                int* __restrict__ off, int N) {
    __shared__ int sh[1024];
    __shared__ int carry;
    int t = threadIdx.x;
    if (t == 0) carry = 0;
    __syncthreads();
    for (int base = 0; base < N; base += 1024) {
        int v = (base + t < N) ? deg[base + t] : 0;
        sh[t] = v;
        __syncthreads();
        for (int o = 1; o < 1024; o <<= 1) {
            int x = (t >= o) ? sh[t - o] : 0;
            __syncthreads();
            sh[t] += x;
            __syncthreads();
        }
        int excl = sh[t] - v + carry;
        if (base + t < N) off[base + t] = excl;
        __syncthreads();
        if (t == 1023) carry += sh[1023];
        __syncthreads();
    }
    if (t == 0) off[N] = carry;
}

__global__ void csr_fill_kernel(const int* __restrict__ ei, int E, int N,
                                const int* __restrict__ off,
                                int* __restrict__ cur,
                                int* __restrict__ csrc) {
    int i = blockIdx.x * blockDim.x + threadIdx.x;
    int ET = E + N;
    if (i >= ET) return;
    int s, d;
    if (i < E) { s = ei[i]; d = ei[E + i]; } else { s = d = i - E; }
    int pos = atomicAdd(&cur[d], 1);
    csrc[off[d] + pos] = s;
}

// ------ batched fp16 wmma GEMM: CTA 144x128, 6 warps, warp 48x64, BK=64 ----
#define BM 144
#define BN 128
#define BK 64
#define TGEMM 192
#define A_LD 72
#define B_LD 136
#define A_TILE_B 20736u      // 144*72*2
#define B_TILE_B 17408u      // 64*136*2
#define ST_A 0u
#define ST_B A_TILE_B
#define STAGE_B (A_TILE_B + B_TILE_B)   // 38144
#define SMEM_GEMM_BYTES (2 * STAGE_B)   // 76288 -> 2 CTAs/SM

__global__ void __launch_bounds__(TGEMM, 2)
gemm_wmma_fp16_kernel(int K, int Nn,
                      const hf* __restrict__ Ag0, const hf* __restrict__ Bg0,
                      float* __restrict__ C0,
                      size_t strideA, size_t strideB, size_t strideC) {
    extern __shared__ char smem[];
    const uint32_t sb = smem_u32(smem);
    const int tid = threadIdx.x;
    const int bn = blockIdx.x, bm = blockIdx.y;
    const size_t z = blockIdx.z;
    const hf* Ag = Ag0 + z * strideA;
    const hf* Bg = Bg0 + z * strideB;
    float* C = C0 + z * strideC;

    const int warpId = tid >> 5;          // 0..5
    const int wm = warpId % 3;            // 3 row groups of 48
    const int wn = warpId / 3;            // 2 col groups of 64
    const int nk = K >> 6;

    const size_t aBase = (size_t)(bm * BM);
    const int cCol = bn * BN;

    auto load_stage = [&](int kt, uint32_t stg) {
        // A: 144 rows x 8 segs -> 1152 chunks, 6 iters x 192 threads (exact)
#pragma unroll
        for (int i = 0; i < 6; i++) {
            int idx = tid + i * TGEMM;
            int ar = idx >> 3, as = (idx & 7) << 3;
            cp_async16(sb + stg + ST_A + (uint32_t)(ar * A_LD + as) * 2,
                       Ag + (aBase + ar) * K + kt * BK + as);
        }
        // B: 64 rows x 16 segs -> 1024 chunks, 6 guarded iters
#pragma unroll
        for (int i = 0; i < 6; i++) {
            int idx = tid + i * TGEMM;
            if (idx < 1024) {
                int br = idx >> 4, bs = (idx & 15) << 3;
                cp_async16(sb + stg + ST_B + (uint32_t)(br * B_LD + bs) * 2,
                           Bg + (size_t)(kt * BK + br) * Nn + cCol + bs);
            }
        }
        CP_COMMIT();
    };

    wmma::fragment<wmma::accumulator, 16, 16, 16, float> acc[3][4];
#pragma unroll
    for (int i = 0; i < 3; i++)
#pragma unroll
        for (int j = 0; j < 4; j++) wmma::fill_fragment(acc[i][j], 0.0f);

    load_stage(0, 0);

    for (int kt = 0; kt < nk; kt++) {
        const uint32_t stg = (kt & 1) ? STAGE_B : 0u;
        if (kt + 1 < nk) {
            load_stage(kt + 1, (kt & 1) ? 0u : STAGE_B);
            CP_WAIT(1);
        } else {
            CP_WAIT(0);
        }
        __syncthreads();

        const hf* sA = (const hf*)(smem + stg + ST_A);
        const hf* sB = (const hf*)(smem + stg + ST_B);

#pragma unroll
        for (int kk = 0; kk < BK; kk += 16) {
            wmma::fragment<wmma::matrix_a, 16, 16, 16, hf, wmma::row_major> af[3];
#pragma unroll
            for (int i = 0; i < 3; i++)
                wmma::load_matrix_sync(af[i], sA + (wm * 48 + i * 16) * A_LD + kk, A_LD);
#pragma unroll
            for (int j = 0; j < 4; j++) {
                wmma::fragment<wmma::matrix_b, 16, 16, 16, hf, wmma::row_major> bf;
                wmma::load_matrix_sync(bf, sB + kk * B_LD + wn * 64 + j * 16, B_LD);
#pragma unroll
                for (int i = 0; i < 3; i++)
                    wmma::mma_sync(acc[i][j], af[i], bf, acc[i][j]);
            }
        }
        __syncthreads();
    }

#pragma unroll
    for (int i = 0; i < 3; i++) {
        int row = bm * BM + wm * 48 + i * 16;
#pragma unroll
        for (int j = 0; j < 4; j++) {
            int col = cCol + wn * 64 + j * 16;
            wmma::store_matrix_sync(&C[(size_t)row * Nn + col], acc[i][j],
                                    Nn, wmma::mem_row_major);
        }
    }
}

// ---------------------------- attention scores (batched) -------------------
__global__ void att_scores_kernel(const float* __restrict__ Hbase, size_t hstride,
                                  const float* __restrict__ s0, const float* __restrict__ d0,
                                  const float* __restrict__ s1, const float* __restrict__ d1,
                                  float* __restrict__ a_s_base,
                                  float* __restrict__ a_d_base, int N) {
    int n = blockIdx.x;
    if (n >= N) return;
    int z = blockIdx.y;
    const float* Hf = Hbase + (size_t)z * hstride;
    const float* att_s = z ? s1 : s0;
    const float* att_d = z ? d1 : d0;
    float* a_s = a_s_base + (size_t)z * NMAX * 4;
    float* a_d = a_d_base + (size_t)z * NMAX * 4;

    int h = threadIdx.y;
    int lane = threadIdx.x;
    const float* row = Hf + (size_t)n * F512 + h * C128;
    float ss = 0.f, sd = 0.f;
#pragma unroll
    for (int j = 0; j < 4; j++) {
        int c = lane + 32 * j;
        float v = row[c];
        ss += v * att_s[h * C128 + c];
        sd += v * att_d[h * C128 + c];
    }
#pragma unroll
    for (int o = 16; o > 0; o >>= 1) {
        ss += __shfl_down_sync(0xffffffffu, ss, o);
        sd += __shfl_down_sync(0xffffffffu, sd, o);
    }
    if (lane == 0) { a_s[n * 4 + h] = ss; a_d[n * 4 + h] = sd; }
}

// ---------------- fused per-dst softmax + aggregation (batched) ------------
__device__ __forceinline__ float leaky(float e) { return e > 0.f ? e : 0.2f * e; }

__global__ __launch_bounds__(256)
void gat_attn_kernel(const float* __restrict__ Hbase, size_t hstride,
                     const float4* __restrict__ a_s_base,
                     const float4* __restrict__ a_d_base,
                     const int* __restrict__ off,
                     const int* __restrict__ deg_arr,
                     const int* __restrict__ csrc,
                     const float* __restrict__ bias0,
                     const float* __restrict__ bias1,
                     hf* __restrict__ outh,
                     float* __restrict__ outf, size_t ostride,
                     size_t oslot) {
    int d = blockIdx.x;
    int z = blockIdx.y;
    int t = threadIdx.x;
    int lane = t & 31, wid = t >> 5;

    const float* Hf = Hbase + (size_t)z * hstride;
    const float4* a_s4 = a_s_base + (size_t)z * NMAX;
    const float4* a_d4 = a_d_base + (size_t)z * NMAX;
    const float* bias = z ? bias1 : bias0;

    __shared__ int   s_list[CAP];
    __shared__ float w[CAP][4];
    __shared__ float red[8][4];
    __shared__ float mx_s[4], invd_s[4];

    const int start = off[d];
    const int deg = deg_arr[d];
    const float4 ad = a_d4[d];

    float m0 = -1e30f, m1 = -1e30f, m2 = -1e30f, m3 = -1e30f;
    for (int j = t; j < deg; j += 256) {
        int s = csrc[start + j];
        float4 as = a_s4[s];
        float e0 = leaky(as.x + ad.x);
        float e1 = leaky(as.y + ad.y);
        float e2 = leaky(as.z + ad.z);
        float e3 = leaky(as.w + ad.w);
        if (j < CAP) {
            s_list[j] = s;
            w[j][0] = e0; w[j][1] = e1; w[j][2] = e2; w[j][3] = e3;
        }
        m0 = fmaxf(m0, e0); m1 = fmaxf(m1, e1);
        m2 = fmaxf(m2, e2); m3 = fmaxf(m3, e3);
    }
#pragma unroll
    for (int o = 16; o > 0; o >>= 1) {
        m0 = fmaxf(m0, __shfl_xor_sync(0xffffffffu, m0, o));
        m1 = fmaxf(m1, __shfl_xor_sync(0xffffffffu, m1, o));
        m2 = fmaxf(m2, __shfl_xor_sync(0xffffffffu, m2, o));
        m3 = fmaxf(m3, __shfl_xor_sync(0xffffffffu, m3, o));
    }
    if (lane == 0) { red[wid][0] = m0; red[wid][1] = m1; red[wid][2] = m2; red[wid][3] = m3; }
    __syncthreads();
    if (t < 4) {
        float mm = -1e30f;
#pragma unroll
        for (int k = 0; k < 8; k++) mm = fmaxf(mm, red[k][t]);
        mx_s[t] = mm;
    }
    __syncthreads();
    const float mx0 = mx_s[0], mx1 = mx_s[1], mx2 = mx_s[2], mx3 = mx_s[3];

    float s0 = 0.f, s1 = 0.f, s2 = 0.f, s3 = 0.f;
    for (int j = t; j < deg; j += 256) {
        float e0, e1, e2, e3;
        if (j < CAP) {
            e0 = w[j][0]; e1 = w[j][1]; e2 = w[j][2]; e3 = w[j][3];
        } else {
            int s = csrc[start + j];
            float4 as = a_s4[s];
            e0 = leaky(as.x + ad.x); e1 = leaky(as.y + ad.y);
            e2 = leaky(as.z + ad.z); e3 = leaky(as.w + ad.w);
        }
        float x0 = expf(e0 - mx0), x1 = expf(e1 - mx1);
        float x2 = expf(e2 - mx2), x3 = expf(e3 - mx3);
        if (j < CAP) { w[j][0] = x0; w[j][1] = x1; w[j][2] = x2; w[j][3] = x3; }
        s0 += x0; s1 += x1; s2 += x2; s3 += x3;
    }
#pragma unroll
    for (int o = 16; o > 0; o >>= 1) {
        s0 += __shfl_xor_sync(0xffffffffu, s0, o);
        s1 += __shfl_xor_sync(0xffffffffu, s1, o);
        s2 += __shfl_xor_sync(0xffffffffu, s2, o);
        s3 += __shfl_xor_sync(0xffffffffu, s3, o);
    }
    __syncthreads();
    if (lane == 0) { red[wid][0] = s0; red[wid][1] = s1; red[wid][2] = s2; red[wid][3] = s3; }
    __syncthreads();
    if (t < 4) {
        float ssum = 0.f;
#pragma unroll
        for (int k = 0; k < 8; k++) ssum += red[k][t];
        invd_s[t] = 1.0f / (ssum + 1e-16f);
    }
    __syncthreads();

    // ---- phase C: 4-way unrolled weighted gather (MLP=4) ----
    const int c2 = t * 2;
    const int h = c2 >> 7;
    const float inv = invd_s[h];
    const float mxh = mx_s[h];
    float acc0 = 0.f, acc1 = 0.f;
    const int mdeg = (deg < CAP) ? deg : CAP;
    int j = 0;
    for (; j + 4 <= mdeg; j += 4) {
        int sA = s_list[j],     sB = s_list[j + 1];
        int sC = s_list[j + 2], sD = s_list[j + 3];
        float wA = w[j][h],     wB = w[j + 1][h];
        float wC = w[j + 2][h], wD = w[j + 3][h];
        float2 vA = *(const float2*)(Hf + (size_t)sA * F512 + c2);
        float2 vB = *(const float2*)(Hf + (size_t)sB * F512 + c2);
        float2 vC = *(const float2*)(Hf + (size_t)sC * F512 + c2);
        float2 vD = *(const float2*)(Hf + (size_t)sD * F512 + c2);
        float aA = wA * inv, aB = wB * inv, aC = wC * inv, aD = wD * inv;
        acc0 += vA.x * aA + vB.x * aB + vC.x * aC + vD.x * aD;
        acc1 += vA.y * aA + vB.y * aB + vC.y * aC + vD.y * aD;
    }
    for (; j < mdeg; j++) {
        int s = s_list[j];
        float alpha = w[j][h] * inv;
        float2 v = *(const float2*)(Hf + (size_t)s * F512 + c2);
        acc0 += v.x * alpha;
        acc1 += v.y * alpha;
    }
    for (; j < deg; j++) {   // spill path (deg > CAP)
        int s = csrc[start + j];
        const float* asp = (const float*)&a_s4[s];
        const float* adp = (const float*)&ad;
        float ww = expf(leaky(asp[h] + adp[h]) - mxh);
        float alpha = ww * inv;
        float2 v = *(const float2*)(Hf + (size_t)s * F512 + c2);
        acc0 += v.x * alpha;
        acc1 += v.y * alpha;
    }
    if (outh) {
        acc0 = fmaxf(acc0 + bias[c2], 0.f);
        acc1 = fmaxf(acc1 + bias[c2 + 1], 0.f);
        size_t o = (size_t)z * oslot + (size_t)d * F512 + c2;
        *(__half2*)(outh + o) = __floats2half2_rn(acc0, acc1);
    } else {
        size_t o = (size_t)z * ostride + (size_t)d * F512 + c2;
        *(float2*)(outf + o) = make_float2(acc0, acc1);
    }
}

// layer-2 epilogue (batched)
__global__ void head_mean_norm_kernel(const float* __restrict__ aggr_base, size_t astride,
                                      const float* __restrict__ bias0,
                                      const float* __restrict__ bias1,
                                      float* __restrict__ outq,
                                      float* __restrict__ outk, int B) {
    int n = blockIdx.x;
    if (n >= B) return;
    int z = blockIdx.y;
    const float* aggr = aggr_base + (size_t)z * astride;
    const float* bias = z ? bias1 : bias0;
    float* outv = z ? outk : outq;
    int c = threadIdx.x;
    size_t base = (size_t)n * F512;
    float v = 0.25f * (aggr[base + c] + aggr[base + 128 + c] +
                       aggr[base + 256 + c] + aggr[base + 384 + c]) + bias[c];
    float s = v * v;
#pragma unroll
    for (int o = 16; o > 0; o >>= 1) s += __shfl_down_sync(0xffffffffu, s, o);
    __shared__ float red[4];
    if ((c & 31) == 0) red[c >> 5] = s;
    __syncthreads();
    float tot = red[0] + red[1] + red[2] + red[3];
    outv[(size_t)n * C128 + c] = v * rsqrtf(tot + 1e-24f);
}

// ---------------- logits: tiled fp32 GEMM out[B,1+R] ------------------------
#define LT 64
__global__ __launch_bounds__(256)
void logits_gemm_kernel(const float* __restrict__ q,
                        const float* __restrict__ kv,
                        const float* __restrict__ queue,
                        float* __restrict__ out, int B, int R,
                        long tail_off, long tail_len) {
    __shared__ float qt[LT][33];
    __shared__ float kt[32][LT + 4];
    const int tid = threadIdx.x;
    const int bx = blockIdx.x, by = blockIdx.y;
    const int tx = tid & 15, ty = tid >> 4;

    float acc[4][4];
#pragma unroll
    for (int i = 0; i < 4; i++)
#pragma unroll
        for (int j = 0; j < 4; j++) acc[i][j] = 0.f;

    for (int k0 = 0; k0 < 128; k0 += 32) {
#pragma unroll
        for (int i = 0; i < 8; i++) {
            int e = tid + i * 256;
            int r = e >> 5, c = e & 31;
            int gr = by * LT + r;
            qt[r][c] = (gr < B) ? q[(size_t)gr * 128 + k0 + c] : 0.f;
        }
#pragma unroll
        for (int i = 0; i < 8; i++) {
            int e = tid + i * 256;
            int r = e >> 6, c = e & 63;
            int gc = bx * LT + c;
            kt[r][c] = (gc < R) ? queue[(size_t)(k0 + r) * R + gc] : 0.f;
        }
        __syncthreads();
#pragma unroll
        for (int k = 0; k < 32; k++) {
            float ra[4], rb[4];
#pragma unroll
            for (int i = 0; i < 4; i++) ra[i] = qt[ty * 4 + i][k];
#pragma unroll
            for (int j = 0; j < 4; j++) rb[j] = kt[k][tx * 4 + j];
#pragma unroll
            for (int i = 0; i < 4; i++)
#pragma unroll
                for (int j = 0; j < 4; j++) acc[i][j] += ra[i] * rb[j];
        }
        __syncthreads();
    }

#pragma unroll
    for (int i = 0; i < 4; i++) {
        int row = by * LT + ty * 4 + i;
        if (row >= B) continue;
#pragma unroll
        for (int j = 0; j < 4; j++) {
            int col = bx * LT + tx * 4 + j;
            if (col < R)
                out[(size_t)row * (R + 1) + 1 + col] = acc[i][j] * 5.0f;
        }
    }

    if (bx == 0 && tid < LT) {
        int n = by * LT + tid;
        if (n < B) {
            const float* qr = q + (size_t)n * 128;
            const float* kr = kv + (size_t)n * 128;
            float s = 0.f;
#pragma unroll 4
            for (int c = 0; c < 128; c++) s += qr[c] * kr[c];
            out[(size_t)n * (R + 1)] = s * 5.0f;
        }
    }
    if (bx == 0 && by == 0) {
        for (long i = tid; i < tail_len; i += 256) out[tail_off + i] = 0.f;
    }
}

// ------------------------------- launch ------------------------------------
extern "C" void kernel_launch(void* const* d_in, const int* in_sizes, int n_in,
                              void* d_out, int out_size) {
    int base = n_in - 17;

    const float* im_q = (const float*)d_in[0];
    const float* im_k = (const float*)d_in[1];
    const int*   ei   = (const int*)d_in[2];

    const float* Wq1  = (const float*)d_in[base + 0];
    const float* asq1 = (const float*)d_in[base + 1];
    const float* adq1 = (const float*)d_in[base + 2];
    const float* bq1  = (const float*)d_in[base + 3];
    const float* Wq2  = (const float*)d_in[base + 4];
    const float* asq2 = (const float*)d_in[base + 5];
    const float* adq2 = (const float*)d_in[base + 6];
    const float* bq2  = (const float*)d_in[base + 7];
    const float* Wk1  = (const float*)d_in[base + 8];
    const float* ask1 = (const float*)d_in[base + 9];
    const float* adk1 = (const float*)d_in[base + 10];
    const float* bk1  = (const float*)d_in[base + 11];
    const float* Wk2  = (const float*)d_in[base + 12];
    const float* ask2 = (const float*)d_in[base + 13];
    const float* adk2 = (const float*)d_in[base + 14];
    const float* bk2  = (const float*)d_in[base + 15];
    const float* queue= (const float*)d_in[base + 16];

    int G = in_sizes[base] / F512;
    int N = in_sizes[0] / G;
    int E = in_sizes[2] / 2;
    int R = in_sizes[base + 16] / C128;
    int B = (out_size % (R + 2) == 0) ? out_size / (R + 2) : out_size / (R + 1);
    if (B > N) B = N;
    int ET = E + N;
    int Mp = (N + BM - 1) / BM * BM;
    if (Mp > MPAD) Mp = MPAD;
    int Kp1 = (G + 63) & ~63;

    float *Hbuf, *asrc, *adst, *seedq, *seedk, *aggr2;
    float *ask1m, *adk1m, *bk1m, *ask2m, *adk2m, *bk2m;
    int *deg, *off, *cur, *csrc;
    hf *A1, *A2, *W1, *W2;
    cudaGetSymbolAddress((void**)&Hbuf, g_H);
    cudaGetSymbolAddress((void**)&asrc, g_asrc);
    cudaGetSymbolAddress((void**)&adst, g_adst);
    cudaGetSymbolAddress((void**)&seedq, g_seedq);
    cudaGetSymbolAddress((void**)&seedk, g_seedk);
    cudaGetSymbolAddress((void**)&aggr2, g_aggr2);
    cudaGetSymbolAddress((void**)&ask1m, g_ask1m);
    cudaGetSymbolAddress((void**)&adk1m, g_adk1m);
    cudaGetSymbolAddress((void**)&bk1m, g_bk1m);
    cudaGetSymbolAddress((void**)&ask2m, g_ask2m);
    cudaGetSymbolAddress((void**)&adk2m, g_adk2m);
    cudaGetSymbolAddress((void**)&bk2m, g_bk2m);
    cudaGetSymbolAddress((void**)&deg, g_deg);
    cudaGetSymbolAddress((void**)&off, g_off);
    cudaGetSymbolAddress((void**)&cur, g_cur);
    cudaGetSymbolAddress((void**)&csrc, g_csrc);
    cudaGetSymbolAddress((void**)&A1, g_A1);
    cudaGetSymbolAddress((void**)&A2, g_A2);
    cudaGetSymbolAddress((void**)&W1, g_W1);
    cudaGetSymbolAddress((void**)&W2, g_W2);

    cudaFuncSetAttribute(gemm_wmma_fp16_kernel,
                         cudaFuncAttributeMaxDynamicSharedMemorySize, SMEM_GEMM_BYTES);

    const size_t a1slot = (size_t)Mp * Kp1;
    const size_t a2slot = (size_t)MPAD * F512;
    const size_t hslot  = (size_t)MPAD * F512;
    const size_t w1slot = (size_t)Kp1 * F512;
    const size_t w2slot = (size_t)F512 * F512;
    const size_t aggr2slot = (size_t)NMAX * F512 / 4;   // >= B*512

    long totA1 = (long)Mp * Kp1;
    long wtot = 2 * (long)w1slot + 2 * (long)w2slot;

    // 1) input convert (batched q/k)
    conv_pad2_kernel<<<dim3((unsigned)((totA1 + 255) / 256), 2), 256>>>(
        im_q, im_k, N, G, Kp1, totA1, A1);
    // 2) all weight converts (+momentum blend for key)
    wconv_all_kernel<<<(int)((wtot + 255) / 256), 256>>>(
        Wq1, Wk1, Wq2, Wk2, G, Kp1, W1, W2);
    // 3) misc prep
    misc_prep_kernel<<<(2 * N + 2688 + 255) / 256, 256>>>(
        N, deg, cur,
        ask1, asq1, adk1, adq1, bk1, bq1,
        ask2, asq2, adk2, adq2, bk2, bq2,
        ask1m, adk1m, bk1m, ask2m, adk2m, bk2m);
    // 4) layer-1 GEMM (batched)
    {
        dim3 grid(F512 / BN, Mp / BM, 2);
        gemm_wmma_fp16_kernel<<<grid, TGEMM, SMEM_GEMM_BYTES>>>(
            Kp1, F512, A1, W1, Hbuf, a1slot, w1slot, hslot);
    }
    // 5-7) CSR
    csr_count_kernel<<<(ET + 255) / 256, 256>>>(ei, E, N, deg);
    csr_scan_kernel<<<1, 1024>>>(deg, off, N);
    csr_fill_kernel<<<(ET + 255) / 256, 256>>>(ei, E, N, off, cur, csrc);
    // 8-9) layer-1 attention -> fp16 A2 (pad rows stay zero from init)
    att_scores_kernel<<<dim3(N, 2), dim3(32, 4)>>>(Hbuf, hslot, asq1, adq1, ask1m, adk1m,
                                                   asrc, adst, N);
    gat_attn_kernel<<<dim3(N, 2), 256>>>(Hbuf, hslot, (const float4*)asrc,
                                         (const float4*)adst, off, deg, csrc,
                                         bq1, bk1m, A2, nullptr, 0, a2slot);
    // 10) layer-2 GEMM (batched)
    {
        dim3 grid(F512 / BN, Mp / BM, 2);
        gemm_wmma_fp16_kernel<<<grid, TGEMM, SMEM_GEMM_BYTES>>>(
            F512, F512, A2, W2, Hbuf, a2slot, w2slot, hslot);
    }
    // 11-12) layer-2 attention (dst < B only), fp32 out
    att_scores_kernel<<<dim3(N, 2), dim3(32, 4)>>>(Hbuf, hslot, asq2, adq2, ask2m, adk2m,
                                                   asrc, adst, N);
    gat_attn_kernel<<<dim3(B, 2), 256>>>(Hbuf, hslot, (const float4*)asrc,
                                         (const float4*)adst, off, deg, csrc,
                                         nullptr, nullptr, nullptr,
                                         aggr2, aggr2slot, 0);
    // 13) head-mean + l2norm
    head_mean_norm_kernel<<<dim3(B, 2), 128>>>(aggr2, aggr2slot, bq2, bk2m,
                                               seedq, seedk, B);
    // 14) logits
    {
        long written = (long)B * (R + 1);
        long tail = (long)out_size - written;
        if (tail < 0) tail = 0;
        dim3 grid((R + LT - 1) / LT, (B + LT - 1) / LT);
        logits_gemm_kernel<<<grid, 256>>>(seedq, seedk, queue, (float*)d_out,
                                          B, R, written, tail);
    }
}

// round 17
// speedup vs baseline: 1.1349x; 1.0594x over previous
#include <cuda_runtime.h>
#include <cuda_fp16.h>
#include <mma.h>
#include <cstdint>

using namespace nvcuda;

// ---------------------------------------------------------------------------
// MoCoGraph: two 2-layer GAT encoders + MoCo logits.
// GEMMs: fp16 single-pass wmma (fp32 accum), CTA 144x128, 6 warps,
//        warp tile 48x64, BK=64 cp.async double-buffer, fp32 out.
// Attention: CSR gather over fp32 H, phase-C 4-way unrolled (MLP=4).
// CSR build + misc prep forked onto a side stream, hidden under layer-1 GEMM.
// Logits: smem-tiled fp32 GEMM.
// ---------------------------------------------------------------------------

#define NMAX   10240
#define MPAD   10368
#define ETMAX  180224
#define F512   512
#define C128   128
#define CAP    512
#define KPAD1  1024

typedef __half hf;

// ------------------------- device scratch (no mallocs) ---------------------
__device__ float g_H  [2 * (size_t)MPAD * F512];
__device__ hf    g_A1 [2 * (size_t)MPAD * KPAD1];
__device__ hf    g_A2 [2 * (size_t)MPAD * F512];   // pad rows stay 0 (zero-init)
__device__ hf    g_W1 [2 * KPAD1 * F512];
__device__ hf    g_W2 [2 * F512 * F512];
__device__ float g_asrc[2 * NMAX * 4];
__device__ float g_adst[2 * NMAX * 4];
__device__ float g_seedq[(size_t)NMAX * C128];
__device__ float g_seedk[(size_t)NMAX * C128];
__device__ float g_ask1m[F512], g_adk1m[F512], g_bk1m[F512];
__device__ float g_ask2m[F512], g_adk2m[F512], g_bk2m[C128];
__device__ int g_deg[NMAX];
__device__ int g_off[NMAX + 1];
__device__ int g_cur[NMAX];
__device__ int g_csrc[ETMAX];
__device__ float g_aggr2[2 * (size_t)NMAX * F512 / 4];

// ------------------------------ helpers ------------------------------------
__device__ __forceinline__ uint32_t smem_u32(const void* p) {
    uint32_t a;
    asm("{ .reg .u64 t; cvta.to.shared.u64 t, %1; cvt.u32.u64 %0, t; }" : "=r"(a) : "l"(p));
    return a;
}
__device__ __forceinline__ void cp_async16(uint32_t s, const void* g) {
    asm volatile("cp.async.cg.shared.global [%0], [%1], 16;" :: "r"(s), "l"(g));
}
#define CP_COMMIT() asm volatile("cp.async.commit_group;" ::: "memory")
#define CP_WAIT(n)  asm volatile("cp.async.wait_group %0;" :: "n"(n) : "memory")

// ------------------------------ prep kernels -------------------------------
__global__ void conv_pad2_kernel(const float* __restrict__ in0,
                                 const float* __restrict__ in1,
                                 int M, int K, int Kp, long total,
                                 hf* __restrict__ out) {
    long idx = (long)blockIdx.x * blockDim.x + threadIdx.x;
    if (idx >= total) return;
    const float* in = blockIdx.y ? in1 : in0;
    size_t o = (size_t)blockIdx.y * total + idx;
    int r = (int)(idx / Kp), c = (int)(idx % Kp);
    float v = (r < M && c < K) ? in[(size_t)r * K + c] : 0.f;
    out[o] = __float2half_rn(v);
}

__global__ void wconv_all_kernel(const float* __restrict__ Wq1,
                                 const float* __restrict__ Wk1,
                                 const float* __restrict__ Wq2,
                                 const float* __restrict__ Wk2,
                                 int G, int Kp1,
                                 hf* __restrict__ W1, hf* __restrict__ W2) {
    long idx = (long)blockIdx.x * blockDim.x + threadIdx.x;
    const long s1 = (long)Kp1 * F512;
    const long s2 = (long)F512 * F512;
    if (idx < 2 * s1) {
        int z = idx >= s1;
        long j = idx - (long)z * s1;
        int r = (int)(j / F512);
        float v = 0.f;
        if (r < G) v = z ? (0.99f * Wk1[j] + 0.01f * Wq1[j]) : Wq1[j];
        W1[idx] = __float2half_rn(v);
    } else if (idx < 2 * s1 + 2 * s2) {
        long j2 = idx - 2 * s1;
        int z = j2 >= s2;
        long j = j2 - (long)z * s2;
        float v = z ? (0.99f * Wk2[j] + 0.01f * Wq2[j]) : Wq2[j];
        W2[j2] = __float2half_rn(v);
    }
}

__global__ void misc_prep_kernel(int N,
                                 int* __restrict__ deg, int* __restrict__ cur,
                                 const float* ask1, const float* asq1,
                                 const float* adk1, const float* adq1,
                                 const float* bk1,  const float* bq1,
                                 const float* ask2, const float* asq2,
                                 const float* adk2, const float* adq2,
                                 const float* bk2,  const float* bq2,
                                 float* o1, float* o2, float* o3,
                                 float* o4, float* o5, float* o6) {
    int idx = blockIdx.x * blockDim.x + threadIdx.x;
    if (idx < N) { deg[idx] = 0; return; }
    if (idx < 2 * N) { cur[idx - N] = 0; return; }
    int j = idx - 2 * N;
    if (j < 512)       o1[j]        = 0.99f * ask1[j]        + 0.01f * asq1[j];
    else if (j < 1024) o2[j - 512]  = 0.99f * adk1[j - 512]  + 0.01f * adq1[j - 512];
    else if (j < 1536) o3[j - 1024] = 0.99f * bk1[j - 1024]  + 0.01f * bq1[j - 1024];
    else if (j < 2048) o4[j - 1536] = 0.99f * ask2[j - 1536] + 0.01f * asq2[j - 1536];
    else if (j < 2560) o5[j - 2048] = 0.99f * adk2[j - 2048] + 0.01f * adq2[j - 2048];
    else if (j < 2688) o6[j - 2560] = 0.99f * bk2[j - 2560]  + 0.01f * bq2[j - 2560];
}

// ------------------------------- CSR build ---------------------------------
__global__ void csr_count_kernel(const int* __restrict__ ei, int E, int N,
                                 int* __restrict__ deg) {
    int i = blockIdx.x * blockDim.x + threadIdx.x;
    int ET = E + N;
    if (i >= ET) return;
    int d = (i < E) ? ei[E + i] : (i - E);
    atomicAdd(&deg[d], 1);
}

__global__ void csr_scan_kernel(const int* __restrict__ deg,
                                int* __restrict__ off, int N) {
    __shared__ int sh[1024];
    __shared__ int carry;
    int t = threadIdx.x;
    if (t == 0) carry = 0;
    __syncthreads();
    for (int base = 0; base < N; base += 1024) {
        int v = (base + t < N) ? deg[base + t] : 0;
        sh[t] = v;
        __syncthreads();
        for (int o = 1; o < 1024; o <<= 1) {
            int x = (t >= o) ? sh[t - o] : 0;
            __syncthreads();
            sh[t] += x;
            __syncthreads();
        }
        int excl = sh[t] - v + carry;
        if (base + t < N) off[base + t] = excl;
        __syncthreads();
        if (t == 1023) carry += sh[1023];
        __syncthreads();
    }
    if (t == 0) off[N] = carry;
}

__global__ void csr_fill_kernel(const int* __restrict__ ei, int E, int N,
                                const int* __restrict__ off,
                                int* __restrict__ cur,
                                int* __restrict__ csrc) {
    int i = blockIdx.x * blockDim.x + threadIdx.x;
    int ET = E + N;
    if (i >= ET) return;
    int s, d;
    if (i < E) { s = ei[i]; d = ei[E + i]; } else { s = d = i - E; }
    int pos = atomicAdd(&cur[d], 1);
    csrc[off[d] + pos] = s;
}

// ------ batched fp16 wmma GEMM: CTA 144x128, 6 warps, warp 48x64, BK=64 ----
#define BM 144
#define BN 128
#define BK 64
#define TGEMM 192
#define A_LD 72
#define B_LD 136
#define A_TILE_B 20736u
#define B_TILE_B 17408u
#define ST_A 0u
#define ST_B A_TILE_B
#define STAGE_B (A_TILE_B + B_TILE_B)
#define SMEM_GEMM_BYTES (2 * STAGE_B)

__global__ void __launch_bounds__(TGEMM, 2)
gemm_wmma_fp16_kernel(int K, int Nn,
                      const hf* __restrict__ Ag0, const hf* __restrict__ Bg0,
                      float* __restrict__ C0,
                      size_t strideA, size_t strideB, size_t strideC) {
    extern __shared__ char smem[];
    const uint32_t sb = smem_u32(smem);
    const int tid = threadIdx.x;
    const int bn = blockIdx.x, bm = blockIdx.y;
    const size_t z = blockIdx.z;
    const hf* Ag = Ag0 + z * strideA;
    const hf* Bg = Bg0 + z * strideB;
    float* C = C0 + z * strideC;

    const int warpId = tid >> 5;
    const int wm = warpId % 3;
    const int wn = warpId / 3;
    const int nk = K >> 6;

    const size_t aBase = (size_t)(bm * BM);
    const int cCol = bn * BN;

    auto load_stage = [&](int kt, uint32_t stg) {
#pragma unroll
        for (int i = 0; i < 6; i++) {
            int idx = tid + i * TGEMM;
            int ar = idx >> 3, as = (idx & 7) << 3;
            cp_async16(sb + stg + ST_A + (uint32_t)(ar * A_LD + as) * 2,
                       Ag + (aBase + ar) * K + kt * BK + as);
        }
#pragma unroll
        for (int i = 0; i < 6; i++) {
            int idx = tid + i * TGEMM;
            if (idx < 1024) {
                int br = idx >> 4, bs = (idx & 15) << 3;
                cp_async16(sb + stg + ST_B + (uint32_t)(br * B_LD + bs) * 2,
                           Bg + (size_t)(kt * BK + br) * Nn + cCol + bs);
            }
        }
        CP_COMMIT();
    };

    wmma::fragment<wmma::accumulator, 16, 16, 16, float> acc[3][4];
#pragma unroll
    for (int i = 0; i < 3; i++)
#pragma unroll
        for (int j = 0; j < 4; j++) wmma::fill_fragment(acc[i][j], 0.0f);

    load_stage(0, 0);

    for (int kt = 0; kt < nk; kt++) {
        const uint32_t stg = (kt & 1) ? STAGE_B : 0u;
        if (kt + 1 < nk) {
            load_stage(kt + 1, (kt & 1) ? 0u : STAGE_B);
            CP_WAIT(1);
        } else {
            CP_WAIT(0);
        }
        __syncthreads();

        const hf* sA = (const hf*)(smem + stg + ST_A);
        const hf* sB = (const hf*)(smem + stg + ST_B);

#pragma unroll
        for (int kk = 0; kk < BK; kk += 16) {
            wmma::fragment<wmma::matrix_a, 16, 16, 16, hf, wmma::row_major> af[3];
#pragma unroll
            for (int i = 0; i < 3; i++)
                wmma::load_matrix_sync(af[i], sA + (wm * 48 + i * 16) * A_LD + kk, A_LD);
#pragma unroll
            for (int j = 0; j < 4; j++) {
                wmma::fragment<wmma::matrix_b, 16, 16, 16, hf, wmma::row_major> bf;
                wmma::load_matrix_sync(bf, sB + kk * B_LD + wn * 64 + j * 16, B_LD);
#pragma unroll
                for (int i = 0; i < 3; i++)
                    wmma::mma_sync(acc[i][j], af[i], bf, acc[i][j]);
            }
        }
        __syncthreads();
    }

#pragma unroll
    for (int i = 0; i < 3; i++) {
        int row = bm * BM + wm * 48 + i * 16;
#pragma unroll
        for (int j = 0; j < 4; j++) {
            int col = cCol + wn * 64 + j * 16;
            wmma::store_matrix_sync(&C[(size_t)row * Nn + col], acc[i][j],
                                    Nn, wmma::mem_row_major);
        }
    }
}

// ---------------------------- attention scores (batched) -------------------
__global__ void att_scores_kernel(const float* __restrict__ Hbase, size_t hstride,
                                  const float* __restrict__ s0, const float* __restrict__ d0,
                                  const float* __restrict__ s1, const float* __restrict__ d1,
                                  float* __restrict__ a_s_base,
                                  float* __restrict__ a_d_base, int N) {
    int n = blockIdx.x;
    if (n >= N) return;
    int z = blockIdx.y;
    const float* Hf = Hbase + (size_t)z * hstride;
    const float* att_s = z ? s1 : s0;
    const float* att_d = z ? d1 : d0;
    float* a_s = a_s_base + (size_t)z * NMAX * 4;
    float* a_d = a_d_base + (size_t)z * NMAX * 4;

    int h = threadIdx.y;
    int lane = threadIdx.x;
    const float* row = Hf + (size_t)n * F512 + h * C128;
    float ss = 0.f, sd = 0.f;
#pragma unroll
    for (int j = 0; j < 4; j++) {
        int c = lane + 32 * j;
        float v = row[c];
        ss += v * att_s[h * C128 + c];
        sd += v * att_d[h * C128 + c];
    }
#pragma unroll
    for (int o = 16; o > 0; o >>= 1) {
        ss += __shfl_down_sync(0xffffffffu, ss, o);
        sd += __shfl_down_sync(0xffffffffu, sd, o);
    }
    if (lane == 0) { a_s[n * 4 + h] = ss; a_d[n * 4 + h] = sd; }
}

// ---------------- fused per-dst softmax + aggregation (batched) ------------
__device__ __forceinline__ float leaky(float e) { return e > 0.f ? e : 0.2f * e; }

__global__ __launch_bounds__(256)
void gat_attn_kernel(const float* __restrict__ Hbase, size_t hstride,
                     const float4* __restrict__ a_s_base,
                     const float4* __restrict__ a_d_base,
                     const int* __restrict__ off,
                     const int* __restrict__ deg_arr,
                     const int* __restrict__ csrc,
                     const float* __restrict__ bias0,
                     const float* __restrict__ bias1,
                     hf* __restrict__ outh,
                     float* __restrict__ outf, size_t ostride,
                     size_t oslot) {
    int d = blockIdx.x;
    int z = blockIdx.y;
    int t = threadIdx.x;
    int lane = t & 31, wid = t >> 5;

    const float* Hf = Hbase + (size_t)z * hstride;
    const float4* a_s4 = a_s_base + (size_t)z * NMAX;
    const float4* a_d4 = a_d_base + (size_t)z * NMAX;
    const float* bias = z ? bias1 : bias0;

    __shared__ int   s_list[CAP];
    __shared__ float w[CAP][4];
    __shared__ float red[8][4];
    __shared__ float mx_s[4], invd_s[4];

    const int start = off[d];
    const int deg = deg_arr[d];
    const float4 ad = a_d4[d];

    float m0 = -1e30f, m1 = -1e30f, m2 = -1e30f, m3 = -1e30f;
    for (int j = t; j < deg; j += 256) {
        int s = csrc[start + j];
        float4 as = a_s4[s];
        float e0 = leaky(as.x + ad.x);
        float e1 = leaky(as.y + ad.y);
        float e2 = leaky(as.z + ad.z);
        float e3 = leaky(as.w + ad.w);
        if (j < CAP) {
            s_list[j] = s;
            w[j][0] = e0; w[j][1] = e1; w[j][2] = e2; w[j][3] = e3;
        }
        m0 = fmaxf(m0, e0); m1 = fmaxf(m1, e1);
        m2 = fmaxf(m2, e2); m3 = fmaxf(m3, e3);
    }
#pragma unroll
    for (int o = 16; o > 0; o >>= 1) {
        m0 = fmaxf(m0, __shfl_xor_sync(0xffffffffu, m0, o));
        m1 = fmaxf(m1, __shfl_xor_sync(0xffffffffu, m1, o));
        m2 = fmaxf(m2, __shfl_xor_sync(0xffffffffu, m2, o));
        m3 = fmaxf(m3, __shfl_xor_sync(0xffffffffu, m3, o));
    }
    if (lane == 0) { red[wid][0] = m0; red[wid][1] = m1; red[wid][2] = m2; red[wid][3] = m3; }
    __syncthreads();
    if (t < 4) {
        float mm = -1e30f;
#pragma unroll
        for (int k = 0; k < 8; k++) mm = fmaxf(mm, red[k][t]);
        mx_s[t] = mm;
    }
    __syncthreads();
    const float mx0 = mx_s[0], mx1 = mx_s[1], mx2 = mx_s[2], mx3 = mx_s[3];

    float s0 = 0.f, s1 = 0.f, s2 = 0.f, s3 = 0.f;
    for (int j = t; j < deg; j += 256) {
        float e0, e1, e2, e3;
        if (j < CAP) {
            e0 = w[j][0]; e1 = w[j][1]; e2 = w[j][2]; e3 = w[j][3];
        } else {
            int s = csrc[start + j];
            float4 as = a_s4[s];
            e0 = leaky(as.x + ad.x); e1 = leaky(as.y + ad.y);
            e2 = leaky(as.z + ad.z); e3 = leaky(as.w + ad.w);
        }
        float x0 = expf(e0 - mx0), x1 = expf(e1 - mx1);
        float x2 = expf(e2 - mx2), x3 = expf(e3 - mx3);
        if (j < CAP) { w[j][0] = x0; w[j][1] = x1; w[j][2] = x2; w[j][3] = x3; }
        s0 += x0; s1 += x1; s2 += x2; s3 += x3;
    }
#pragma unroll
    for (int o = 16; o > 0; o >>= 1) {
        s0 += __shfl_xor_sync(0xffffffffu, s0, o);
        s1 += __shfl_xor_sync(0xffffffffu, s1, o);
        s2 += __shfl_xor_sync(0xffffffffu, s2, o);
        s3 += __shfl_xor_sync(0xffffffffu, s3, o);
    }
    __syncthreads();
    if (lane == 0) { red[wid][0] = s0; red[wid][1] = s1; red[wid][2] = s2; red[wid][3] = s3; }
    __syncthreads();
    if (t < 4) {
        float ssum = 0.f;
#pragma unroll
        for (int k = 0; k < 8; k++) ssum += red[k][t];
        invd_s[t] = 1.0f / (ssum + 1e-16f);
    }
    __syncthreads();

    // ---- phase C: 4-way unrolled weighted gather (MLP=4) ----
    const int c2 = t * 2;
    const int h = c2 >> 7;
    const float inv = invd_s[h];
    const float mxh = mx_s[h];
    float acc0 = 0.f, acc1 = 0.f;
    const int mdeg = (deg < CAP) ? deg : CAP;
    int j = 0;
    for (; j + 4 <= mdeg; j += 4) {
        int sA = s_list[j],     sB = s_list[j + 1];
        int sC = s_list[j + 2], sD = s_list[j + 3];
        float wA = w[j][h],     wB = w[j + 1][h];
        float wC = w[j + 2][h], wD = w[j + 3][h];
        float2 vA = *(const float2*)(Hf + (size_t)sA * F512 + c2);
        float2 vB = *(const float2*)(Hf + (size_t)sB * F512 + c2);
        float2 vC = *(const float2*)(Hf + (size_t)sC * F512 + c2);
        float2 vD = *(const float2*)(Hf + (size_t)sD * F512 + c2);
        float aA = wA * inv, aB = wB * inv, aC = wC * inv, aD = wD * inv;
        acc0 += vA.x * aA + vB.x * aB + vC.x * aC + vD.x * aD;
        acc1 += vA.y * aA + vB.y * aB + vC.y * aC + vD.y * aD;
    }
    for (; j < mdeg; j++) {
        int s = s_list[j];
        float alpha = w[j][h] * inv;
        float2 v = *(const float2*)(Hf + (size_t)s * F512 + c2);
        acc0 += v.x * alpha;
        acc1 += v.y * alpha;
    }
    for (; j < deg; j++) {
        int s = csrc[start + j];
        const float* asp = (const float*)&a_s4[s];
        const float* adp = (const float*)&ad;
        float ww = expf(leaky(asp[h] + adp[h]) - mxh);
        float alpha = ww * inv;
        float2 v = *(const float2*)(Hf + (size_t)s * F512 + c2);
        acc0 += v.x * alpha;
        acc1 += v.y * alpha;
    }
    if (outh) {
        acc0 = fmaxf(acc0 + bias[c2], 0.f);
        acc1 = fmaxf(acc1 + bias[c2 + 1], 0.f);
        size_t o = (size_t)z * oslot + (size_t)d * F512 + c2;
        *(__half2*)(outh + o) = __floats2half2_rn(acc0, acc1);
    } else {
        size_t o = (size_t)z * ostride + (size_t)d * F512 + c2;
        *(float2*)(outf + o) = make_float2(acc0, acc1);
    }
}

// layer-2 epilogue (batched)
__global__ void head_mean_norm_kernel(const float* __restrict__ aggr_base, size_t astride,
                                      const float* __restrict__ bias0,
                                      const float* __restrict__ bias1,
                                      float* __restrict__ outq,
                                      float* __restrict__ outk, int B) {
    int n = blockIdx.x;
    if (n >= B) return;
    int z = blockIdx.y;
    const float* aggr = aggr_base + (size_t)z * astride;
    const float* bias = z ? bias1 : bias0;
    float* outv = z ? outk : outq;
    int c = threadIdx.x;
    size_t base = (size_t)n * F512;
    float v = 0.25f * (aggr[base + c] + aggr[base + 128 + c] +
                       aggr[base + 256 + c] + aggr[base + 384 + c]) + bias[c];
    float s = v * v;
#pragma unroll
    for (int o = 16; o > 0; o >>= 1) s += __shfl_down_sync(0xffffffffu, s, o);
    __shared__ float red[4];
    if ((c & 31) == 0) red[c >> 5] = s;
    __syncthreads();
    float tot = red[0] + red[1] + red[2] + red[3];
    outv[(size_t)n * C128 + c] = v * rsqrtf(tot + 1e-24f);
}

// ---------------- logits: tiled fp32 GEMM out[B,1+R] ------------------------
#define LT 64
__global__ __launch_bounds__(256)
void logits_gemm_kernel(const float* __restrict__ q,
                        const float* __restrict__ kv,
                        const float* __restrict__ queue,
                        float* __restrict__ out, int B, int R,
                        long tail_off, long tail_len) {
    __shared__ float qt[LT][33];
    __shared__ float kt[32][LT + 4];
    const int tid = threadIdx.x;
    const int bx = blockIdx.x, by = blockIdx.y;
    const int tx = tid & 15, ty = tid >> 4;

    float acc[4][4];
#pragma unroll
    for (int i = 0; i < 4; i++)
#pragma unroll
        for (int j = 0; j < 4; j++) acc[i][j] = 0.f;

    for (int k0 = 0; k0 < 128; k0 += 32) {
#pragma unroll
        for (int i = 0; i < 8; i++) {
            int e = tid + i * 256;
            int r = e >> 5, c = e & 31;
            int gr = by * LT + r;
            qt[r][c] = (gr < B) ? q[(size_t)gr * 128 + k0 + c] : 0.f;
        }
#pragma unroll
        for (int i = 0; i < 8; i++) {
            int e = tid + i * 256;
            int r = e >> 6, c = e & 63;
            int gc = bx * LT + c;
            kt[r][c] = (gc < R) ? queue[(size_t)(k0 + r) * R + gc] : 0.f;
        }
        __syncthreads();
#pragma unroll
        for (int k = 0; k < 32; k++) {
            float ra[4], rb[4];
#pragma unroll
            for (int i = 0; i < 4; i++) ra[i] = qt[ty * 4 + i][k];
#pragma unroll
            for (int j = 0; j < 4; j++) rb[j] = kt[k][tx * 4 + j];
#pragma unroll
            for (int i = 0; i < 4; i++)
#pragma unroll
                for (int j = 0; j < 4; j++) acc[i][j] += ra[i] * rb[j];
        }
        __syncthreads();
    }

#pragma unroll
    for (int i = 0; i < 4; i++) {
        int row = by * LT + ty * 4 + i;
        if (row >= B) continue;
#pragma unroll
        for (int j = 0; j < 4; j++) {
            int col = bx * LT + tx * 4 + j;
            if (col < R)
                out[(size_t)row * (R + 1) + 1 + col] = acc[i][j] * 5.0f;
        }
    }

    if (bx == 0 && tid < LT) {
        int n = by * LT + tid;
        if (n < B) {
            const float* qr = q + (size_t)n * 128;
            const float* kr = kv + (size_t)n * 128;
            float s = 0.f;
#pragma unroll 4
            for (int c = 0; c < 128; c++) s += qr[c] * kr[c];
            out[(size_t)n * (R + 1)] = s * 5.0f;
        }
    }
    if (bx == 0 && by == 0) {
        for (long i = tid; i < tail_len; i += 256) out[tail_off + i] = 0.f;
    }
}

// ------------------------------- launch ------------------------------------
extern "C" void kernel_launch(void* const* d_in, const int* in_sizes, int n_in,
                              void* d_out, int out_size) {
    int base = n_in - 17;

    const float* im_q = (const float*)d_in[0];
    const float* im_k = (const float*)d_in[1];
    const int*   ei   = (const int*)d_in[2];

    const float* Wq1  = (const float*)d_in[base + 0];
    const float* asq1 = (const float*)d_in[base + 1];
    const float* adq1 = (const float*)d_in[base + 2];
    const float* bq1  = (const float*)d_in[base + 3];
    const float* Wq2  = (const float*)d_in[base + 4];
    const float* asq2 = (const float*)d_in[base + 5];
    const float* adq2 = (const float*)d_in[base + 6];
    const float* bq2  = (const float*)d_in[base + 7];
    const float* Wk1  = (const float*)d_in[base + 8];
    const float* ask1 = (const float*)d_in[base + 9];
    const float* adk1 = (const float*)d_in[base + 10];
    const float* bk1  = (const float*)d_in[base + 11];
    const float* Wk2  = (const float*)d_in[base + 12];
    const float* ask2 = (const float*)d_in[base + 13];
    const float* adk2 = (const float*)d_in[base + 14];
    const float* bk2  = (const float*)d_in[base + 15];
    const float* queue= (const float*)d_in[base + 16];

    int G = in_sizes[base] / F512;
    int N = in_sizes[0] / G;
    int E = in_sizes[2] / 2;
    int R = in_sizes[base + 16] / C128;
    int B = (out_size % (R + 2) == 0) ? out_size / (R + 2) : out_size / (R + 1);
    if (B > N) B = N;
    int ET = E + N;
    int Mp = (N + BM - 1) / BM * BM;
    if (Mp > MPAD) Mp = MPAD;
    int Kp1 = (G + 63) & ~63;

    float *Hbuf, *asrc, *adst, *seedq, *seedk, *aggr2;
    float *ask1m, *adk1m, *bk1m, *ask2m, *adk2m, *bk2m;
    int *deg, *off, *cur, *csrc;
    hf *A1, *A2, *W1, *W2;
    cudaGetSymbolAddress((void**)&Hbuf, g_H);
    cudaGetSymbolAddress((void**)&asrc, g_asrc);
    cudaGetSymbolAddress((void**)&adst, g_adst);
    cudaGetSymbolAddress((void**)&seedq, g_seedq);
    cudaGetSymbolAddress((void**)&seedk, g_seedk);
    cudaGetSymbolAddress((void**)&aggr2, g_aggr2);
    cudaGetSymbolAddress((void**)&ask1m, g_ask1m);
    cudaGetSymbolAddress((void**)&adk1m, g_adk1m);
    cudaGetSymbolAddress((void**)&bk1m, g_bk1m);
    cudaGetSymbolAddress((void**)&ask2m, g_ask2m);
    cudaGetSymbolAddress((void**)&adk2m, g_adk2m);
    cudaGetSymbolAddress((void**)&bk2m, g_bk2m);
    cudaGetSymbolAddress((void**)&deg, g_deg);
    cudaGetSymbolAddress((void**)&off, g_off);
    cudaGetSymbolAddress((void**)&cur, g_cur);
    cudaGetSymbolAddress((void**)&csrc, g_csrc);
    cudaGetSymbolAddress((void**)&A1, g_A1);
    cudaGetSymbolAddress((void**)&A2, g_A2);
    cudaGetSymbolAddress((void**)&W1, g_W1);
    cudaGetSymbolAddress((void**)&W2, g_W2);

    cudaFuncSetAttribute(gemm_wmma_fp16_kernel,
                         cudaFuncAttributeMaxDynamicSharedMemorySize, SMEM_GEMM_BYTES);

    // side stream + events, created once on the (uncaptured) correctness call
    static cudaStream_t s1 = nullptr;
    static cudaEvent_t evF = nullptr, evJ = nullptr;
    if (s1 == nullptr) {
        cudaStreamCreateWithFlags(&s1, cudaStreamNonBlocking);
        cudaEventCreateWithFlags(&evF, cudaEventDisableTiming);
        cudaEventCreateWithFlags(&evJ, cudaEventDisableTiming);
    }

    const size_t a1slot = (size_t)Mp * Kp1;
    const size_t a2slot = (size_t)MPAD * F512;
    const size_t hslot  = (size_t)MPAD * F512;
    const size_t w1slot = (size_t)Kp1 * F512;
    const size_t w2slot = (size_t)F512 * F512;
    const size_t aggr2slot = (size_t)NMAX * F512 / 4;

    long totA1 = (long)Mp * Kp1;
    long wtot = 2 * (long)w1slot + 2 * (long)w2slot;

    // ---- fork side stream: misc prep + CSR build (independent of GEMM) ----
    cudaEventRecord(evF, 0);
    cudaStreamWaitEvent(s1, evF, 0);
    misc_prep_kernel<<<(2 * N + 2688 + 255) / 256, 256, 0, s1>>>(
        N, deg, cur,
        ask1, asq1, adk1, adq1, bk1, bq1,
        ask2, asq2, adk2, adq2, bk2, bq2,
        ask1m, adk1m, bk1m, ask2m, adk2m, bk2m);
    csr_count_kernel<<<(ET + 255) / 256, 256, 0, s1>>>(ei, E, N, deg);
    csr_scan_kernel<<<1, 1024, 0, s1>>>(deg, off, N);
    csr_fill_kernel<<<(ET + 255) / 256, 256, 0, s1>>>(ei, E, N, off, cur, csrc);
    cudaEventRecord(evJ, s1);

    // ---- main stream: operand prep + layer-1 GEMM ----
    conv_pad2_kernel<<<dim3((unsigned)((totA1 + 255) / 256), 2), 256>>>(
        im_q, im_k, N, G, Kp1, totA1, A1);
    wconv_all_kernel<<<(int)((wtot + 255) / 256), 256>>>(
        Wq1, Wk1, Wq2, Wk2, G, Kp1, W1, W2);
    {
        dim3 grid(F512 / BN, Mp / BM, 2);
        gemm_wmma_fp16_kernel<<<grid, TGEMM, SMEM_GEMM_BYTES>>>(
            Kp1, F512, A1, W1, Hbuf, a1slot, w1slot, hslot);
    }

    // ---- join: attention needs CSR + blended vectors + H ----
    cudaStreamWaitEvent(0, evJ, 0);

    att_scores_kernel<<<dim3(N, 2), dim3(32, 4)>>>(Hbuf, hslot, asq1, adq1, ask1m, adk1m,
                                                   asrc, adst, N);
    gat_attn_kernel<<<dim3(N, 2), 256>>>(Hbuf, hslot, (const float4*)asrc,
                                         (const float4*)adst, off, deg, csrc,
                                         bq1, bk1m, A2, nullptr, 0, a2slot);
    {
        dim3 grid(F512 / BN, Mp / BM, 2);
        gemm_wmma_fp16_kernel<<<grid, TGEMM, SMEM_GEMM_BYTES>>>(
            F512, F512, A2, W2, Hbuf, a2slot, w2slot, hslot);
    }
    att_scores_kernel<<<dim3(N, 2), dim3(32, 4)>>>(Hbuf, hslot, asq2, adq2, ask2m, adk2m,
                                                   asrc, adst, N);
    gat_attn_kernel<<<dim3(B, 2), 256>>>(Hbuf, hslot, (const float4*)asrc,
                                         (const float4*)adst, off, deg, csrc,
                                         nullptr, nullptr, nullptr,
                                         aggr2, aggr2slot, 0);
    head_mean_norm_kernel<<<dim3(B, 2), 128>>>(aggr2, aggr2slot, bq2, bk2m,
                                               seedq, seedk, B);
    {
        long written = (long)B * (R + 1);
        long tail = (long)out_size - written;
        if (tail < 0) tail = 0;
        dim3 grid((R + LT - 1) / LT, (B + LT - 1) / LT);
        logits_gemm_kernel<<<grid, 256>>>(seedq, seedk, queue, (float*)d_out,
                                          B, R, written, tail);
    }
}